// round 11
// baseline (speedup 1.0000x reference)
#include <cuda_runtime.h>
#include <cuda_fp16.h>
#include <cstdint>
#include <math.h>

#define BATCH 8
#define SEQ   1024
#define DIM   2048
#define HEADS 16
#define HD    128
#define MROWS (BATCH*SEQ)
#define QSCALE 0.08838834764831845f

// ---- scratch (device globals) ----
__device__ __align__(256) __half g_Qh[MROWS*DIM];
__device__ __align__(256) __half g_Kh[MROWS*DIM], g_Kl[MROWS*DIM];
__device__ __align__(256) __half g_Vh[MROWS*DIM], g_Vl[MROWS*DIM];
__device__ __align__(256) __half g_Cth[MROWS*DIM];
__device__ __align__(256) __half g_Xqh[MROWS*DIM];
__device__ __align__(256) __half g_Xkh[MROWS*DIM];
__device__ __align__(256) __half g_Wqh[DIM*DIM];
__device__ __align__(256) __half g_Wkh[DIM*DIM];
__device__ __align__(256) __half g_Wvh[DIM*DIM];
__device__ __align__(256) __half g_Woh[DIM*DIM];

// ---- helpers ----
__device__ __forceinline__ unsigned pack_h2(__half a, __half b){ __half2 h=__halves2half2(a,b); return *reinterpret_cast<unsigned*>(&h); }
__device__ __forceinline__ void split_f32(float x, __half& hi, __half& lo){ hi=__float2half_rn(x); lo=__float2half_rn(x-__half2float(hi)); }
__device__ __forceinline__ void mma16816(float* c, const unsigned* a, unsigned b0, unsigned b1){
    asm volatile("mma.sync.aligned.m16n8k16.row.col.f32.f16.f16.f32 {%0,%1,%2,%3},{%4,%5,%6,%7},{%8,%9},{%0,%1,%2,%3};\n"
        : "+f"(c[0]),"+f"(c[1]),"+f"(c[2]),"+f"(c[3]) : "r"(a[0]),"r"(a[1]),"r"(a[2]),"r"(a[3]),"r"(b0),"r"(b1));
}
__device__ __forceinline__ uint32_t smem_u32(const void* p){ uint32_t a; asm("{ .reg .u64 t; cvta.to.shared.u64 t, %1; cvt.u32.u64 %0, t; }":"=r"(a):"l"(p)); return a; }
__device__ __forceinline__ void cp16(uint32_t s, const void* g){ asm volatile("cp.async.cg.shared.global [%0], [%1], 16;"::"r"(s),"l"(g)); }
__device__ __forceinline__ void ldsm4(unsigned* r, uint32_t addr){
    asm volatile("ldmatrix.sync.aligned.m8n8.x4.shared.b16 {%0,%1,%2,%3}, [%4];"
        : "=r"(r[0]),"=r"(r[1]),"=r"(r[2]),"=r"(r[3]) : "r"(addr));
}
__device__ __forceinline__ void ldsm4t(unsigned* r, uint32_t addr){
    asm volatile("ldmatrix.sync.aligned.m8n8.x4.trans.shared.b16 {%0,%1,%2,%3}, [%4];"
        : "=r"(r[0]),"=r"(r[1]),"=r"(r[2]),"=r"(r[3]) : "r"(addr));
}
#define CP_COMMIT() asm volatile("cp.async.commit_group;" ::: "memory")
#define CP_WAIT(n)  asm volatile("cp.async.wait_group %0;" :: "n"(n) : "memory")

// =====================================================================
// HMMA 1-term GEMM body: C = alpha * Ah @ Bh^T (pure fp16 in, fp32 accum)
// CTA 128x128, warp tile 64x32, BK=32, 2-stage cp.async. 2 smem planes.
// =====================================================================
#define GLD 40
#define PLANE_H (128*GLD)
#define STAGE_H (2*PLANE_H)
#define GEMM_SMEM (2*STAGE_H*2)   // 40960 B

__device__ __forceinline__ void gemm_body(
    const __half* __restrict__ Ah_g, const __half* __restrict__ Bh_g,
    float* __restrict__ C, __half* __restrict__ Ch, __half* __restrict__ Cl,
    float alpha, __half* sm)
{
    const uint32_t sbase = smem_u32(sm);
    const int tid = threadIdx.x, lane = tid & 31, wid = tid >> 5;
    const int wm = wid & 1, wn = wid >> 1;
    const int g = lane >> 2, tig = lane & 3;
    const int bm = blockIdx.y * 128, bn = blockIdx.x * 128;

    // loader: 4 chunks/thread (p: 0=A, 1=B)
    const __half* gsrc[4]; uint32_t soff[4];
#pragma unroll
    for (int i = 0; i < 4; i++) {
        int p = i >> 1;
        int sub = (i & 1) * 256 + tid;
        int row = sub >> 2, c = sub & 3;
        const __half* base = (p == 0) ? Ah_g + (size_t)bm * DIM : Bh_g + (size_t)bn * DIM;
        gsrc[i] = base + (size_t)row * DIM + c * 8;
        soff[i] = (uint32_t)(p * PLANE_H + row * GLD + c * 8) * 2;
    }

    float acc[4][4][4];
#pragma unroll
    for (int mf = 0; mf < 4; mf++)
#pragma unroll
        for (int nf = 0; nf < 4; nf++)
#pragma unroll
            for (int r = 0; r < 4; r++) acc[mf][nf][r] = 0.0f;

    const uint32_t a_row0 = (uint32_t)(wm * 64 + (lane & 15));
    const uint32_t a_koff = (uint32_t)((lane >> 4) * 8);
    const uint32_t b_row0 = (uint32_t)(wn * 32 + ((lane >> 3) & 1) * 8 + (lane & 7));

    {
#pragma unroll
        for (int i = 0; i < 4; i++) cp16(sbase + soff[i], gsrc[i]);
        CP_COMMIT();
    }

    for (int kt = 0; kt < DIM / 32; kt++) {
        int s = kt & 1;
        if (kt + 1 < DIM / 32) {
            uint32_t sb2 = sbase + (uint32_t)((s ^ 1) * STAGE_H) * 2;
            const int koff = (kt + 1) * 32;
#pragma unroll
            for (int i = 0; i < 4; i++) cp16(sb2 + soff[i], gsrc[i] + koff);
            CP_COMMIT();
            CP_WAIT(1);
        } else {
            CP_WAIT(0);
        }
        __syncthreads();

        const uint32_t st = sbase + (uint32_t)(s * STAGE_H) * 2;
#pragma unroll
        for (int kk = 0; kk < 2; kk++) {
            unsigned ah[4][4];
#pragma unroll
            for (int mf = 0; mf < 4; mf++) {
                uint32_t ra = st + ((a_row0 + mf * 16) * GLD + kk * 16 + a_koff) * 2;
                ldsm4(ah[mf], ra);
            }
#pragma unroll
            for (int g2 = 0; g2 < 2; g2++) {
                uint32_t rb = st + (PLANE_H + (b_row0 + g2 * 16) * GLD + kk * 16 + a_koff) * 2;
                unsigned bh[4];
                ldsm4(bh, rb);
#pragma unroll
                for (int mf = 0; mf < 4; mf++) {
                    mma16816(acc[mf][2*g2],   ah[mf], bh[0], bh[2]);
                    mma16816(acc[mf][2*g2+1], ah[mf], bh[1], bh[3]);
                }
            }
        }
        __syncthreads();
    }

#pragma unroll
    for (int mf = 0; mf < 4; mf++)
#pragma unroll
        for (int nf = 0; nf < 4; nf++) {
            int row = bm + wm * 64 + mf * 16 + g;
            int col = bn + wn * 32 + nf * 8 + 2 * tig;
            float v0 = acc[mf][nf][0] * alpha, v1 = acc[mf][nf][1] * alpha;
            float v2 = acc[mf][nf][2] * alpha, v3 = acc[mf][nf][3] * alpha;
            if (Ch) {
                __half h0,l0,h1,l1,h2,l2,h3,l3;
                split_f32(v0,h0,l0); split_f32(v1,h1,l1);
                split_f32(v2,h2,l2); split_f32(v3,h3,l3);
                *reinterpret_cast<__half2*>(&Ch[(size_t)row*DIM+col])     = __halves2half2(h0,h1);
                *reinterpret_cast<__half2*>(&Ch[(size_t)(row+8)*DIM+col]) = __halves2half2(h2,h3);
                if (Cl) {
                    *reinterpret_cast<__half2*>(&Cl[(size_t)row*DIM+col])     = __halves2half2(l0,l1);
                    *reinterpret_cast<__half2*>(&Cl[(size_t)(row+8)*DIM+col]) = __halves2half2(l2,l3);
                }
            } else {
                *reinterpret_cast<float2*>(&C[(size_t)row*DIM+col])       = make_float2(v0,v1);
                *reinterpret_cast<float2*>(&C[(size_t)(row+8)*DIM+col])   = make_float2(v2,v3);
            }
        }
}

// fused Q/K/V projections: blockIdx.z selects operand set
__global__ __launch_bounds__(256, 2) void gemm_qkv()
{
    extern __shared__ __half sm[];
    int z = blockIdx.z;
    const __half* A  = (z == 0) ? g_Xqh : g_Xkh;
    const __half* Bh = (z == 0) ? g_Wqh : (z == 1) ? g_Wkh : g_Wvh;
    __half* Ch = (z == 0) ? g_Qh : (z == 1) ? g_Kh : g_Vh;
    __half* Cl = (z == 0) ? (__half*)nullptr : (z == 1) ? g_Kl : g_Vl;
    float alpha = (z == 0) ? QSCALE : 1.0f;
    gemm_body(A, Bh, nullptr, Ch, Cl, alpha, sm);
}

// output projection: fp32 result
__global__ __launch_bounds__(256, 2) void gemm_o(float* __restrict__ out)
{
    extern __shared__ __half sm[];
    gemm_body(g_Cth, g_Woh, out, nullptr, nullptr, 1.0f, sm);
}

// fused fp32 -> fp16 hi (y=0: xq->Xqh, y=1: xkv->Xkh)
__global__ __launch_bounds__(256) void f32toh2(const float4* __restrict__ Xq, const float4* __restrict__ Xkv){
    const float4* X = blockIdx.y ? Xkv : Xq;
    __half2* H = reinterpret_cast<__half2*>(blockIdx.y ? g_Xkh : g_Xqh);
    int i = blockIdx.x * 256 + threadIdx.x;
    float4 v = X[i];
    H[2*i]   = __halves2half2(__float2half_rn(v.x), __float2half_rn(v.y));
    H[2*i+1] = __halves2half2(__float2half_rn(v.z), __float2half_rn(v.w));
}

// fused weight transpose (hi plane only): blockIdx.z selects {Wq,Wk,Wv,Wo}
__global__ __launch_bounds__(256) void transpose_h4(
    const float* __restrict__ W0, const float* __restrict__ W1,
    const float* __restrict__ W2, const float* __restrict__ W3)
{
    __shared__ float t[32][33];
    int z = blockIdx.z;
    const float* W = (z == 0) ? W0 : (z == 1) ? W1 : (z == 2) ? W2 : W3;
    __half* TH = (z == 0) ? g_Wqh : (z == 1) ? g_Wkh : (z == 2) ? g_Wvh : g_Woh;
    int x = blockIdx.x*32 + threadIdx.x, y = blockIdx.y*32 + threadIdx.y;
#pragma unroll
    for (int j = 0; j < 4; j++) t[threadIdx.y + j*8][threadIdx.x] = W[(size_t)(y + j*8)*DIM + x];
    __syncthreads();
    int x2 = blockIdx.y*32 + threadIdx.x, y2 = blockIdx.x*32 + threadIdx.y;
#pragma unroll
    for (int j = 0; j < 4; j++) {
        TH[(size_t)(y2 + j*8)*DIM + x2] = __float2half_rn(t[threadIdx.x][threadIdx.y + j*8]);
    }
}

// =====================================================================
// flash2: FA-2, pre-split fp16, cp.async double buffer, ldmatrix.
// S = Qh*(Kh+Kl); PV 2-term: P-hi*(Vh+Vl). (unchanged)
// =====================================================================
#define FSTG 65536

__global__ __launch_bounds__(256) void flash2()
{
    extern __shared__ char fs[];
    const uint32_t sb = smem_u32(fs);
    const int tid = threadIdx.x, lane = tid & 31, wid = tid >> 5;
    const int g = lane >> 2, tig = lane & 3;
    const int b = blockIdx.z, h = blockIdx.y, qt = blockIdx.x;
    const int t8 = lane >> 3, l7 = lane & 7;

    const size_t qrow0 = (size_t)(b * SEQ + qt * 128);
    const __half* Qg = g_Qh + qrow0 * DIM + h * HD;
    const size_t kvbase = (size_t)b * SEQ * DIM + h * HD;

    const __half* ksrc[16]; uint32_t kdst[16];
#pragma unroll
    for (int i = 0; i < 16; i++) {
        int p = i >> 2;
        int m = tid + 256 * (i & 3);
        int r = m >> 4, c = m & 15;
        const __half* base =
            (p == 0) ? g_Kh + kvbase : (p == 1) ? g_Kl + kvbase :
            (p == 2) ? g_Vh + kvbase : g_Vl + kvbase;
        ksrc[i] = base + (size_t)r * DIM + c * 8;
        kdst[i] = (uint32_t)(p * 16384 + r * 256 + ((c ^ (r & 7)) << 4));
    }

#pragma unroll
    for (int i = 0; i < 8; i++) {
        int n = tid + 256 * i;
        int r = n >> 4, c = n & 15;
        cp16(sb + FSTG + r * 256 + ((c ^ (r & 7)) << 4), Qg + (size_t)r * DIM + c * 8);
    }
    CP_COMMIT();
#pragma unroll
    for (int i = 0; i < 16; i++) cp16(sb + kdst[i], ksrc[i]);
    CP_COMMIT();

    CP_WAIT(1);
    __syncthreads();

    unsigned q[8][4];
#pragma unroll
    for (int kk = 0; kk < 8; kk++) {
        uint32_t row = (uint32_t)(wid * 16 + ((t8 & 1) << 3) + l7);
        uint32_t kc  = (uint32_t)(2 * kk + (t8 >> 1));
        ldsm4(q[kk], sb + FSTG + row * 256 + ((kc ^ (row & 7)) << 4));
    }
    __syncthreads();

    float o[16][4];
#pragma unroll
    for (int i = 0; i < 16; i++) { o[i][0]=o[i][1]=o[i][2]=o[i][3]=0.0f; }
    float m0 = -1e30f, m1 = -1e30f, l0 = 0.0f, l1 = 0.0f;

    for (int kt = 0; kt < SEQ / 64; kt++) {
        int s = kt & 1;
        if (kt + 1 < SEQ / 64) {
            uint32_t dst = sb + (uint32_t)((s ^ 1) * FSTG);
            size_t koff = (size_t)(kt + 1) * 64 * DIM;
#pragma unroll
            for (int i = 0; i < 16; i++) cp16(dst + kdst[i], ksrc[i] + koff);
            CP_COMMIT();
            CP_WAIT(1);
        } else {
            CP_WAIT(0);
        }
        __syncthreads();
        const uint32_t st = sb + (uint32_t)(s * FSTG);

        float sc[8][4];
#pragma unroll
        for (int nf = 0; nf < 8; nf++) { sc[nf][0]=sc[nf][1]=sc[nf][2]=sc[nf][3]=0.0f; }
#pragma unroll
        for (int kk = 0; kk < 8; kk++) {
#pragma unroll
            for (int nb = 0; nb < 4; nb++) {
                uint32_t n  = (uint32_t)(nb * 16 + ((t8 >> 1) << 3) + l7);
                uint32_t kc = (uint32_t)(2 * kk + (t8 & 1));
                uint32_t ak = st + n * 256 + ((kc ^ (n & 7)) << 4);
                unsigned bh[4], bl[4];
                ldsm4(bh, ak);
                ldsm4(bl, ak + 16384);
                mma16816(sc[2*nb],   q[kk], bh[0], bh[1]);
                mma16816(sc[2*nb+1], q[kk], bh[2], bh[3]);
                mma16816(sc[2*nb],   q[kk], bl[0], bl[1]);
                mma16816(sc[2*nb+1], q[kk], bl[2], bl[3]);
            }
        }

        float r0 = -1e30f, r1 = -1e30f;
#pragma unroll
        for (int nf = 0; nf < 8; nf++) { r0 = fmaxf(r0, fmaxf(sc[nf][0], sc[nf][1])); r1 = fmaxf(r1, fmaxf(sc[nf][2], sc[nf][3])); }
        r0 = fmaxf(r0, __shfl_xor_sync(~0u, r0, 1)); r0 = fmaxf(r0, __shfl_xor_sync(~0u, r0, 2));
        r1 = fmaxf(r1, __shfl_xor_sync(~0u, r1, 1)); r1 = fmaxf(r1, __shfl_xor_sync(~0u, r1, 2));
        float mn0 = fmaxf(m0, r0), mn1 = fmaxf(m1, r1);
        float f0 = __expf(m0 - mn0), f1 = __expf(m1 - mn1);
        m0 = mn0; m1 = mn1;
        float rs0 = 0.0f, rs1 = 0.0f;
#pragma unroll
        for (int nf = 0; nf < 8; nf++) {
            sc[nf][0] = __expf(sc[nf][0] - m0); sc[nf][1] = __expf(sc[nf][1] - m0);
            sc[nf][2] = __expf(sc[nf][2] - m1); sc[nf][3] = __expf(sc[nf][3] - m1);
            rs0 += sc[nf][0] + sc[nf][1]; rs1 += sc[nf][2] + sc[nf][3];
        }
        rs0 += __shfl_xor_sync(~0u, rs0, 1); rs0 += __shfl_xor_sync(~0u, rs0, 2);
        rs1 += __shfl_xor_sync(~0u, rs1, 1); rs1 += __shfl_xor_sync(~0u, rs1, 2);
        l0 = l0 * f0 + rs0; l1 = l1 * f1 + rs1;
#pragma unroll
        for (int nf = 0; nf < 16; nf++) { o[nf][0] *= f0; o[nf][1] *= f0; o[nf][2] *= f1; o[nf][3] *= f1; }

#pragma unroll
        for (int kk2 = 0; kk2 < 4; kk2++) {
            const int j0 = 2*kk2, j1 = 2*kk2 + 1;
            unsigned ah_[4] = {
                pack_h2(__float2half_rn(sc[j0][0]), __float2half_rn(sc[j0][1])),
                pack_h2(__float2half_rn(sc[j0][2]), __float2half_rn(sc[j0][3])),
                pack_h2(__float2half_rn(sc[j1][0]), __float2half_rn(sc[j1][1])),
                pack_h2(__float2half_rn(sc[j1][2]), __float2half_rn(sc[j1][3]))};
            uint32_t kr = (uint32_t)(kk2 * 16 + ((t8 & 1) << 3) + l7);
            uint32_t vrow = st + 32768 + kr * 256;
            uint32_t sw7 = (kr & 7);
#pragma unroll
            for (int na = 0; na < 8; na++) {
                uint32_t nblk = (uint32_t)(2 * na + (t8 >> 1));
                uint32_t av = vrow + ((nblk ^ sw7) << 4);
                unsigned vh[4], vl[4];
                ldsm4t(vh, av);
                ldsm4t(vl, av + 16384);
                mma16816(o[2*na],   ah_, vh[0], vh[1]);
                mma16816(o[2*na+1], ah_, vh[2], vh[3]);
                mma16816(o[2*na],   ah_, vl[0], vl[1]);
                mma16816(o[2*na+1], ah_, vl[2], vl[3]);
            }
        }
        __syncthreads();
    }

    float i0 = 1.0f / l0, i1 = 1.0f / l1;
    const size_t row = qrow0 + wid * 16 + g;
    __half* Ch = g_Cth + row * DIM + h * HD;
#pragma unroll
    for (int nf2 = 0; nf2 < 16; nf2++) {
        int c = nf2 * 8 + 2 * tig;
        float v0 = o[nf2][0] * i0, v1 = o[nf2][1] * i0;
        float v2 = o[nf2][2] * i1, v3 = o[nf2][3] * i1;
        *reinterpret_cast<__half2*>(Ch + c)         = __halves2half2(__float2half_rn(v0), __float2half_rn(v1));
        *reinterpret_cast<__half2*>(Ch + 8*DIM + c) = __halves2half2(__float2half_rn(v2), __float2half_rn(v3));
    }
}

// =====================================================================
extern "C" void kernel_launch(void* const* d_in, const int* in_sizes, int n_in,
                              void* d_out, int out_size)
{
    const float* xq  = (const float*)d_in[0];
    const float* xkv = (const float*)d_in[1];
    const float* Wq  = (const float*)d_in[2];
    const float* Wk  = (const float*)d_in[3];
    const float* Wv  = (const float*)d_in[4];
    const float* Wo  = (const float*)d_in[5];
    float* out = (float*)d_out;

    int nb = (MROWS * DIM / 4) / 256;
    f32toh2<<<dim3(nb, 2), 256>>>((const float4*)xq, (const float4*)xkv);
    transpose_h4<<<dim3(DIM/32, DIM/32, 4), dim3(32, 8)>>>(Wq, Wk, Wv, Wo);

    cudaFuncSetAttribute(gemm_qkv, cudaFuncAttributeMaxDynamicSharedMemorySize, GEMM_SMEM);
    cudaFuncSetAttribute(gemm_o,   cudaFuncAttributeMaxDynamicSharedMemorySize, GEMM_SMEM);
    gemm_qkv<<<dim3(DIM/128, MROWS/128, 3), 256, GEMM_SMEM>>>();

    cudaFuncSetAttribute(flash2, cudaFuncAttributeMaxDynamicSharedMemorySize, 2 * FSTG);
    flash2<<<dim3(SEQ/128, HEADS, BATCH), 256, 2 * FSTG>>>();

    gemm_o<<<dim3(DIM/128, MROWS/128), 256, GEMM_SMEM>>>(out);
}

// round 12
// speedup vs baseline: 1.1707x; 1.1707x over previous
#include <cuda_runtime.h>
#include <cuda_fp16.h>
#include <cstdint>
#include <math.h>

#define BATCH 8
#define SEQ   1024
#define DIM   2048
#define HEADS 16
#define HD    128
#define MROWS (BATCH*SEQ)
#define QSCALE 0.08838834764831845f

// ---- scratch (device globals) ----
__device__ __align__(256) __half g_Qh[MROWS*DIM];
__device__ __align__(256) __half g_Kh[MROWS*DIM];
__device__ __align__(256) __half g_Vh[MROWS*DIM], g_Vl[MROWS*DIM];
__device__ __align__(256) __half g_Cth[MROWS*DIM];
__device__ __align__(256) __half g_Xqh[MROWS*DIM];
__device__ __align__(256) __half g_Xkh[MROWS*DIM];
__device__ __align__(256) __half g_Wqh[DIM*DIM], g_Wql[DIM*DIM];
__device__ __align__(256) __half g_Wkh[DIM*DIM], g_Wkl[DIM*DIM];
__device__ __align__(256) __half g_Wvh[DIM*DIM], g_Wvl[DIM*DIM];
__device__ __align__(256) __half g_Woh[DIM*DIM], g_Wol[DIM*DIM];

// ---- helpers ----
__device__ __forceinline__ unsigned pack_h2(__half a, __half b){ __half2 h=__halves2half2(a,b); return *reinterpret_cast<unsigned*>(&h); }
__device__ __forceinline__ void split_f32(float x, __half& hi, __half& lo){ hi=__float2half_rn(x); lo=__float2half_rn(x-__half2float(hi)); }
__device__ __forceinline__ void mma16816(float* c, const unsigned* a, unsigned b0, unsigned b1){
    asm volatile("mma.sync.aligned.m16n8k16.row.col.f32.f16.f16.f32 {%0,%1,%2,%3},{%4,%5,%6,%7},{%8,%9},{%0,%1,%2,%3};\n"
        : "+f"(c[0]),"+f"(c[1]),"+f"(c[2]),"+f"(c[3]) : "r"(a[0]),"r"(a[1]),"r"(a[2]),"r"(a[3]),"r"(b0),"r"(b1));
}
__device__ __forceinline__ uint32_t smem_u32(const void* p){ uint32_t a; asm("{ .reg .u64 t; cvta.to.shared.u64 t, %1; cvt.u32.u64 %0, t; }":"=r"(a):"l"(p)); return a; }
__device__ __forceinline__ void cp16(uint32_t s, const void* g){ asm volatile("cp.async.cg.shared.global [%0], [%1], 16;"::"r"(s),"l"(g)); }
__device__ __forceinline__ void ldsm4(unsigned* r, uint32_t addr){
    asm volatile("ldmatrix.sync.aligned.m8n8.x4.shared.b16 {%0,%1,%2,%3}, [%4];"
        : "=r"(r[0]),"=r"(r[1]),"=r"(r[2]),"=r"(r[3]) : "r"(addr));
}
__device__ __forceinline__ void ldsm4t(unsigned* r, uint32_t addr){
    asm volatile("ldmatrix.sync.aligned.m8n8.x4.trans.shared.b16 {%0,%1,%2,%3}, [%4];"
        : "=r"(r[0]),"=r"(r[1]),"=r"(r[2]),"=r"(r[3]) : "r"(addr));
}
#define CP_COMMIT() asm volatile("cp.async.commit_group;" ::: "memory")
#define CP_WAIT(n)  asm volatile("cp.async.wait_group %0;" :: "n"(n) : "memory")

// =====================================================================
// HMMA 2-term GEMM: C = alpha * Ah @ (Bh+Bl)^T
// CTA 128x128, warp tile 64x32, BK=64 (32 ktiles), 2-stage cp.async.
// Halved ktile count attacks the measured fixed-cost-per-ktile binder.
// =====================================================================
#define BK 64
#define GLD 72                    // 36 words == 4 mod 32 -> conflict-free
#define PLANE_H (128*GLD)         // 9216 halves
#define STAGE_H (3*PLANE_H)       // 27648 halves
#define GEMM_SMEM (2*STAGE_H*2)   // 110592 B (2 CTAs/SM: 221KB < 228KB)
#define NKT (DIM/BK)              // 32

__device__ __forceinline__ void gemm_body(
    const __half* __restrict__ Ah_g,
    const __half* __restrict__ Bh_g, const __half* __restrict__ Bl_g,
    float* __restrict__ C, __half* __restrict__ Ch, __half* __restrict__ Cl,
    float alpha, __half* sm)
{
    const uint32_t sbase = smem_u32(sm);
    const int tid = threadIdx.x, lane = tid & 31, wid = tid >> 5;
    const int wm = wid & 1, wn = wid >> 1;
    const int g = lane >> 2, tig = lane & 3;
    const int bm = blockIdx.y * 128, bn = blockIdx.x * 128;

    // loader: 12 chunks/thread (p: 0=A-hi, 1=B-hi, 2=B-lo), 1024 chunks/plane
    const __half* gsrc[12]; uint32_t soff[12];
#pragma unroll
    for (int i = 0; i < 12; i++) {
        int p = i >> 2;
        int sub = (i & 3) * 256 + tid;      // 0..1023
        int row = sub >> 3, col = sub & 7;  // 8 chunks per 64-half row
        const __half* base =
            (p == 0) ? Ah_g + (size_t)bm * DIM :
            (p == 1) ? Bh_g + (size_t)bn * DIM :
                       Bl_g + (size_t)bn * DIM;
        gsrc[i] = base + (size_t)row * DIM + col * 8;
        soff[i] = (uint32_t)(p * PLANE_H + row * GLD + col * 8) * 2;
    }

    float acc[4][4][4];
#pragma unroll
    for (int mf = 0; mf < 4; mf++)
#pragma unroll
        for (int nf = 0; nf < 4; nf++)
#pragma unroll
            for (int r = 0; r < 4; r++) acc[mf][nf][r] = 0.0f;

    const uint32_t a_row0 = (uint32_t)(wm * 64 + (lane & 15));
    const uint32_t a_koff = (uint32_t)((lane >> 4) * 8);
    const uint32_t b_row0 = (uint32_t)(wn * 32 + ((lane >> 3) & 1) * 8 + (lane & 7));

    {
#pragma unroll
        for (int i = 0; i < 12; i++) cp16(sbase + soff[i], gsrc[i]);
        CP_COMMIT();
    }

    for (int kt = 0; kt < NKT; kt++) {
        int s = kt & 1;
        if (kt + 1 < NKT) {
            uint32_t sb2 = sbase + (uint32_t)((s ^ 1) * STAGE_H) * 2;
            const int koff = (kt + 1) * BK;
#pragma unroll
            for (int i = 0; i < 12; i++) cp16(sb2 + soff[i], gsrc[i] + koff);
            CP_COMMIT();
            CP_WAIT(1);
        } else {
            CP_WAIT(0);
        }
        __syncthreads();

        const uint32_t st = sbase + (uint32_t)(s * STAGE_H) * 2;
#pragma unroll
        for (int kk = 0; kk < 4; kk++) {
            unsigned ah[4][4];
#pragma unroll
            for (int mf = 0; mf < 4; mf++) {
                uint32_t ra = st + ((a_row0 + mf * 16) * GLD + kk * 16 + a_koff) * 2;
                ldsm4(ah[mf], ra);
            }
#pragma unroll
            for (int g2 = 0; g2 < 2; g2++) {
                uint32_t rb = st + (PLANE_H + (b_row0 + g2 * 16) * GLD + kk * 16 + a_koff) * 2;
                unsigned bh[4], bl[4];
                ldsm4(bh, rb);
                ldsm4(bl, rb + PLANE_H * 2);
#pragma unroll
                for (int mf = 0; mf < 4; mf++) {
                    mma16816(acc[mf][2*g2],   ah[mf], bh[0], bh[2]);
                    mma16816(acc[mf][2*g2+1], ah[mf], bh[1], bh[3]);
                }
#pragma unroll
                for (int mf = 0; mf < 4; mf++) {
                    mma16816(acc[mf][2*g2],   ah[mf], bl[0], bl[2]);
                    mma16816(acc[mf][2*g2+1], ah[mf], bl[1], bl[3]);
                }
            }
        }
        __syncthreads();
    }

#pragma unroll
    for (int mf = 0; mf < 4; mf++)
#pragma unroll
        for (int nf = 0; nf < 4; nf++) {
            int row = bm + wm * 64 + mf * 16 + g;
            int col = bn + wn * 32 + nf * 8 + 2 * tig;
            float v0 = acc[mf][nf][0] * alpha, v1 = acc[mf][nf][1] * alpha;
            float v2 = acc[mf][nf][2] * alpha, v3 = acc[mf][nf][3] * alpha;
            if (Ch) {
                __half h0,l0,h1,l1,h2,l2,h3,l3;
                split_f32(v0,h0,l0); split_f32(v1,h1,l1);
                split_f32(v2,h2,l2); split_f32(v3,h3,l3);
                *reinterpret_cast<__half2*>(&Ch[(size_t)row*DIM+col])     = __halves2half2(h0,h1);
                *reinterpret_cast<__half2*>(&Ch[(size_t)(row+8)*DIM+col]) = __halves2half2(h2,h3);
                if (Cl) {
                    *reinterpret_cast<__half2*>(&Cl[(size_t)row*DIM+col])     = __halves2half2(l0,l1);
                    *reinterpret_cast<__half2*>(&Cl[(size_t)(row+8)*DIM+col]) = __halves2half2(l2,l3);
                }
            } else {
                *reinterpret_cast<float2*>(&C[(size_t)row*DIM+col])       = make_float2(v0,v1);
                *reinterpret_cast<float2*>(&C[(size_t)(row+8)*DIM+col])   = make_float2(v2,v3);
            }
        }
}

// fused Q/K/V projections: blockIdx.z selects operand set
// Q: hi only. K: hi only (flash S is 1-term). V: hi+lo (PV 2-term).
__global__ __launch_bounds__(256, 2) void gemm_qkv()
{
    extern __shared__ __half sm[];
    int z = blockIdx.z;
    const __half* A  = (z == 0) ? g_Xqh : g_Xkh;
    const __half* Bh = (z == 0) ? g_Wqh : (z == 1) ? g_Wkh : g_Wvh;
    const __half* Bl = (z == 0) ? g_Wql : (z == 1) ? g_Wkl : g_Wvl;
    __half* Ch = (z == 0) ? g_Qh : (z == 1) ? g_Kh : g_Vh;
    __half* Cl = (z == 2) ? g_Vl : (__half*)nullptr;
    float alpha = (z == 0) ? QSCALE : 1.0f;
    gemm_body(A, Bh, Bl, nullptr, Ch, Cl, alpha, sm);
}

// output projection: fp32 result
__global__ __launch_bounds__(256, 2) void gemm_o(float* __restrict__ out)
{
    extern __shared__ __half sm[];
    gemm_body(g_Cth, g_Woh, g_Wol, out, nullptr, nullptr, 1.0f, sm);
}

// fused fp32 -> fp16 hi (y=0: xq->Xqh, y=1: xkv->Xkh)
__global__ __launch_bounds__(256) void f32toh2(const float4* __restrict__ Xq, const float4* __restrict__ Xkv){
    const float4* X = blockIdx.y ? Xkv : Xq;
    __half2* H = reinterpret_cast<__half2*>(blockIdx.y ? g_Xkh : g_Xqh);
    int i = blockIdx.x * 256 + threadIdx.x;
    float4 v = X[i];
    H[2*i]   = __halves2half2(__float2half_rn(v.x), __float2half_rn(v.y));
    H[2*i+1] = __halves2half2(__float2half_rn(v.z), __float2half_rn(v.w));
}

// fused weight transpose+split: blockIdx.z selects {Wq,Wk,Wv,Wo}
__global__ __launch_bounds__(256) void transpose_split4(
    const float* __restrict__ W0, const float* __restrict__ W1,
    const float* __restrict__ W2, const float* __restrict__ W3)
{
    __shared__ float t[32][33];
    int z = blockIdx.z;
    const float* W = (z == 0) ? W0 : (z == 1) ? W1 : (z == 2) ? W2 : W3;
    __half* TH = (z == 0) ? g_Wqh : (z == 1) ? g_Wkh : (z == 2) ? g_Wvh : g_Woh;
    __half* TL = (z == 0) ? g_Wql : (z == 1) ? g_Wkl : (z == 2) ? g_Wvl : g_Wol;
    int x = blockIdx.x*32 + threadIdx.x, y = blockIdx.y*32 + threadIdx.y;
#pragma unroll
    for (int j = 0; j < 4; j++) t[threadIdx.y + j*8][threadIdx.x] = W[(size_t)(y + j*8)*DIM + x];
    __syncthreads();
    int x2 = blockIdx.y*32 + threadIdx.x, y2 = blockIdx.x*32 + threadIdx.y;
#pragma unroll
    for (int j = 0; j < 4; j++) {
        float v = t[threadIdx.x][threadIdx.y + j*8];
        __half h,l; split_f32(v,h,l);
        TH[(size_t)(y2 + j*8)*DIM + x2] = h;
        TL[(size_t)(y2 + j*8)*DIM + x2] = l;
    }
}

// =====================================================================
// flash2: FA-2. S = Qh*Kh (1-term). PV = P-hi*(Vh+Vl) (2-term).
// 3 planes/stage {Kh,Vh,Vl} = 48KB; 2 stages = 96KB smem.
// =====================================================================
#define FSTG 49152

__global__ __launch_bounds__(256) void flash2()
{
    extern __shared__ char fs[];
    const uint32_t sb = smem_u32(fs);
    const int tid = threadIdx.x, lane = tid & 31, wid = tid >> 5;
    const int g = lane >> 2, tig = lane & 3;
    const int b = blockIdx.z, h = blockIdx.y, qt = blockIdx.x;
    const int t8 = lane >> 3, l7 = lane & 7;

    const size_t qrow0 = (size_t)(b * SEQ + qt * 128);
    const __half* Qg = g_Qh + qrow0 * DIM + h * HD;
    const size_t kvbase = (size_t)b * SEQ * DIM + h * HD;

    // loader: 12 chunks/thread per stage (p: 0=Kh, 1=Vh, 2=Vl)
    const __half* ksrc[12]; uint32_t kdst[12];
#pragma unroll
    for (int i = 0; i < 12; i++) {
        int p = i >> 2;
        int m = tid + 256 * (i & 3);
        int r = m >> 4, c = m & 15;
        const __half* base =
            (p == 0) ? g_Kh + kvbase : (p == 1) ? g_Vh + kvbase : g_Vl + kvbase;
        ksrc[i] = base + (size_t)r * DIM + c * 8;
        kdst[i] = (uint32_t)(p * 16384 + r * 256 + ((c ^ (r & 7)) << 4));
    }

    // prime: Q into stage-1 area, then KV stage 0
#pragma unroll
    for (int i = 0; i < 8; i++) {
        int n = tid + 256 * i;
        int r = n >> 4, c = n & 15;
        cp16(sb + FSTG + r * 256 + ((c ^ (r & 7)) << 4), Qg + (size_t)r * DIM + c * 8);
    }
    CP_COMMIT();
#pragma unroll
    for (int i = 0; i < 12; i++) cp16(sb + kdst[i], ksrc[i]);
    CP_COMMIT();

    CP_WAIT(1);
    __syncthreads();

    unsigned q[8][4];
#pragma unroll
    for (int kk = 0; kk < 8; kk++) {
        uint32_t row = (uint32_t)(wid * 16 + ((t8 & 1) << 3) + l7);
        uint32_t kc  = (uint32_t)(2 * kk + (t8 >> 1));
        ldsm4(q[kk], sb + FSTG + row * 256 + ((kc ^ (row & 7)) << 4));
    }
    __syncthreads();

    float o[16][4];
#pragma unroll
    for (int i = 0; i < 16; i++) { o[i][0]=o[i][1]=o[i][2]=o[i][3]=0.0f; }
    float m0 = -1e30f, m1 = -1e30f, l0 = 0.0f, l1 = 0.0f;

    for (int kt = 0; kt < SEQ / 64; kt++) {
        int s = kt & 1;
        if (kt + 1 < SEQ / 64) {
            uint32_t dst = sb + (uint32_t)((s ^ 1) * FSTG);
            size_t koff = (size_t)(kt + 1) * 64 * DIM;
#pragma unroll
            for (int i = 0; i < 12; i++) cp16(dst + kdst[i], ksrc[i] + koff);
            CP_COMMIT();
            CP_WAIT(1);
        } else {
            CP_WAIT(0);
        }
        __syncthreads();
        const uint32_t st = sb + (uint32_t)(s * FSTG);

        // ---- S = Qh*Kh (1-term) ----
        float sc[8][4];
#pragma unroll
        for (int nf = 0; nf < 8; nf++) { sc[nf][0]=sc[nf][1]=sc[nf][2]=sc[nf][3]=0.0f; }
#pragma unroll
        for (int kk = 0; kk < 8; kk++) {
#pragma unroll
            for (int nb = 0; nb < 4; nb++) {
                uint32_t n  = (uint32_t)(nb * 16 + ((t8 >> 1) << 3) + l7);
                uint32_t kc = (uint32_t)(2 * kk + (t8 & 1));
                uint32_t ak = st + n * 256 + ((kc ^ (n & 7)) << 4);
                unsigned bh[4];
                ldsm4(bh, ak);
                mma16816(sc[2*nb],   q[kk], bh[0], bh[1]);
                mma16816(sc[2*nb+1], q[kk], bh[2], bh[3]);
            }
        }

        // ---- online softmax ----
        float r0 = -1e30f, r1 = -1e30f;
#pragma unroll
        for (int nf = 0; nf < 8; nf++) { r0 = fmaxf(r0, fmaxf(sc[nf][0], sc[nf][1])); r1 = fmaxf(r1, fmaxf(sc[nf][2], sc[nf][3])); }
        r0 = fmaxf(r0, __shfl_xor_sync(~0u, r0, 1)); r0 = fmaxf(r0, __shfl_xor_sync(~0u, r0, 2));
        r1 = fmaxf(r1, __shfl_xor_sync(~0u, r1, 1)); r1 = fmaxf(r1, __shfl_xor_sync(~0u, r1, 2));
        float mn0 = fmaxf(m0, r0), mn1 = fmaxf(m1, r1);
        float f0 = __expf(m0 - mn0), f1 = __expf(m1 - mn1);
        m0 = mn0; m1 = mn1;
        float rs0 = 0.0f, rs1 = 0.0f;
#pragma unroll
        for (int nf = 0; nf < 8; nf++) {
            sc[nf][0] = __expf(sc[nf][0] - m0); sc[nf][1] = __expf(sc[nf][1] - m0);
            sc[nf][2] = __expf(sc[nf][2] - m1); sc[nf][3] = __expf(sc[nf][3] - m1);
            rs0 += sc[nf][0] + sc[nf][1]; rs1 += sc[nf][2] + sc[nf][3];
        }
        rs0 += __shfl_xor_sync(~0u, rs0, 1); rs0 += __shfl_xor_sync(~0u, rs0, 2);
        rs1 += __shfl_xor_sync(~0u, rs1, 1); rs1 += __shfl_xor_sync(~0u, rs1, 2);
        l0 = l0 * f0 + rs0; l1 = l1 * f1 + rs1;
#pragma unroll
        for (int nf = 0; nf < 16; nf++) { o[nf][0] *= f0; o[nf][1] *= f0; o[nf][2] *= f1; o[nf][3] *= f1; }

        // ---- O += P-hi @ (Vh+Vl) ----
#pragma unroll
        for (int kk2 = 0; kk2 < 4; kk2++) {
            const int j0 = 2*kk2, j1 = 2*kk2 + 1;
            unsigned ah_[4] = {
                pack_h2(__float2half_rn(sc[j0][0]), __float2half_rn(sc[j0][1])),
                pack_h2(__float2half_rn(sc[j0][2]), __float2half_rn(sc[j0][3])),
                pack_h2(__float2half_rn(sc[j1][0]), __float2half_rn(sc[j1][1])),
                pack_h2(__float2half_rn(sc[j1][2]), __float2half_rn(sc[j1][3]))};
            uint32_t kr = (uint32_t)(kk2 * 16 + ((t8 & 1) << 3) + l7);
            uint32_t vrow = st + 16384 + kr * 256;
            uint32_t sw7 = (kr & 7);
#pragma unroll
            for (int na = 0; na < 8; na++) {
                uint32_t nblk = (uint32_t)(2 * na + (t8 >> 1));
                uint32_t av = vrow + ((nblk ^ sw7) << 4);
                unsigned vh[4], vl[4];
                ldsm4t(vh, av);
                ldsm4t(vl, av + 16384);
                mma16816(o[2*na],   ah_, vh[0], vh[1]);
                mma16816(o[2*na+1], ah_, vh[2], vh[3]);
                mma16816(o[2*na],   ah_, vl[0], vl[1]);
                mma16816(o[2*na+1], ah_, vl[2], vl[3]);
            }
        }
        __syncthreads();
    }

    float i0 = 1.0f / l0, i1 = 1.0f / l1;
    const size_t row = qrow0 + wid * 16 + g;
    __half* Ch = g_Cth + row * DIM + h * HD;
#pragma unroll
    for (int nf2 = 0; nf2 < 16; nf2++) {
        int c = nf2 * 8 + 2 * tig;
        float v0 = o[nf2][0] * i0, v1 = o[nf2][1] * i0;
        float v2 = o[nf2][2] * i1, v3 = o[nf2][3] * i1;
        *reinterpret_cast<__half2*>(Ch + c)         = __halves2half2(__float2half_rn(v0), __float2half_rn(v1));
        *reinterpret_cast<__half2*>(Ch + 8*DIM + c) = __halves2half2(__float2half_rn(v2), __float2half_rn(v3));
    }
}

// =====================================================================
extern "C" void kernel_launch(void* const* d_in, const int* in_sizes, int n_in,
                              void* d_out, int out_size)
{
    const float* xq  = (const float*)d_in[0];
    const float* xkv = (const float*)d_in[1];
    const float* Wq  = (const float*)d_in[2];
    const float* Wk  = (const float*)d_in[3];
    const float* Wv  = (const float*)d_in[4];
    const float* Wo  = (const float*)d_in[5];
    float* out = (float*)d_out;

    int nb = (MROWS * DIM / 4) / 256;
    f32toh2<<<dim3(nb, 2), 256>>>((const float4*)xq, (const float4*)xkv);
    transpose_split4<<<dim3(DIM/32, DIM/32, 4), dim3(32, 8)>>>(Wq, Wk, Wv, Wo);

    cudaFuncSetAttribute(gemm_qkv, cudaFuncAttributeMaxDynamicSharedMemorySize, GEMM_SMEM);
    cudaFuncSetAttribute(gemm_o,   cudaFuncAttributeMaxDynamicSharedMemorySize, GEMM_SMEM);
    gemm_qkv<<<dim3(DIM/128, MROWS/128, 3), 256, GEMM_SMEM>>>();

    cudaFuncSetAttribute(flash2, cudaFuncAttributeMaxDynamicSharedMemorySize, 2 * FSTG);
    flash2<<<dim3(SEQ/128, HEADS, BATCH), 256, 2 * FSTG>>>();

    gemm_o<<<dim3(DIM/128, MROWS/128), 256, GEMM_SMEM>>>(out);
}

// round 13
// speedup vs baseline: 1.8417x; 1.5731x over previous
#include <cuda_runtime.h>
#include <cuda_fp16.h>
#include <cstdint>
#include <math.h>

#define BATCH 8
#define SEQ   1024
#define DIM   2048
#define HEADS 16
#define HD    128
#define MROWS (BATCH*SEQ)
#define QSCALE 0.08838834764831845f

// ---- scratch (device globals) ----
__device__ __align__(256) __half g_Qh[MROWS*DIM];
__device__ __align__(256) __half g_Kh[MROWS*DIM];
__device__ __align__(256) __half g_Vh[MROWS*DIM], g_Vl[MROWS*DIM];
__device__ __align__(256) __half g_Cth[MROWS*DIM];
__device__ __align__(256) __half g_Xqh[MROWS*DIM];
__device__ __align__(256) __half g_Xkh[MROWS*DIM];
__device__ __align__(256) __half g_Wqh[DIM*DIM];
__device__ __align__(256) __half g_Wkh[DIM*DIM];
__device__ __align__(256) __half g_Wvh[DIM*DIM];
__device__ __align__(256) __half g_Woh[DIM*DIM];

// ---- helpers ----
__device__ __forceinline__ unsigned pack_h2(__half a, __half b){ __half2 h=__halves2half2(a,b); return *reinterpret_cast<unsigned*>(&h); }
__device__ __forceinline__ void split_f32(float x, __half& hi, __half& lo){ hi=__float2half_rn(x); lo=__float2half_rn(x-__half2float(hi)); }
__device__ __forceinline__ void mma16816(float* c, const unsigned* a, unsigned b0, unsigned b1){
    asm volatile("mma.sync.aligned.m16n8k16.row.col.f32.f16.f16.f32 {%0,%1,%2,%3},{%4,%5,%6,%7},{%8,%9},{%0,%1,%2,%3};\n"
        : "+f"(c[0]),"+f"(c[1]),"+f"(c[2]),"+f"(c[3]) : "r"(a[0]),"r"(a[1]),"r"(a[2]),"r"(a[3]),"r"(b0),"r"(b1));
}
__device__ __forceinline__ uint32_t smem_u32(const void* p){ uint32_t a; asm("{ .reg .u64 t; cvta.to.shared.u64 t, %1; cvt.u32.u64 %0, t; }":"=r"(a):"l"(p)); return a; }
__device__ __forceinline__ void cp16(uint32_t s, const void* g){ asm volatile("cp.async.cg.shared.global [%0], [%1], 16;"::"r"(s),"l"(g)); }
__device__ __forceinline__ void ldsm4(unsigned* r, uint32_t addr){
    asm volatile("ldmatrix.sync.aligned.m8n8.x4.shared.b16 {%0,%1,%2,%3}, [%4];"
        : "=r"(r[0]),"=r"(r[1]),"=r"(r[2]),"=r"(r[3]) : "r"(addr));
}
__device__ __forceinline__ void ldsm4t(unsigned* r, uint32_t addr){
    asm volatile("ldmatrix.sync.aligned.m8n8.x4.trans.shared.b16 {%0,%1,%2,%3}, [%4];"
        : "=r"(r[0]),"=r"(r[1]),"=r"(r[2]),"=r"(r[3]) : "r"(addr));
}
#define CP_COMMIT() asm volatile("cp.async.commit_group;" ::: "memory")
#define CP_WAIT(n)  asm volatile("cp.async.wait_group %0;" :: "n"(n) : "memory")

// =====================================================================
// HMMA 1-term GEMM: C = alpha * Ah @ Bh^T
// CTA 128x128, warp tile 64x32, BK=64 (32 ktiles), 2-stage cp.async.
// =====================================================================
#define BK 64
#define GLD 72                    // 36 words == 4 mod 32 -> conflict-free
#define PLANE_H (128*GLD)         // 9216 halves
#define STAGE_H (2*PLANE_H)       // 18432 halves
#define GEMM_SMEM (2*STAGE_H*2)   // 73728 B
#define NKT (DIM/BK)              // 32

__device__ __forceinline__ void gemm_body(
    const __half* __restrict__ Ah_g, const __half* __restrict__ Bh_g,
    float* __restrict__ C, __half* __restrict__ Ch, __half* __restrict__ Cl,
    float alpha, __half* sm)
{
    const uint32_t sbase = smem_u32(sm);
    const int tid = threadIdx.x, lane = tid & 31, wid = tid >> 5;
    const int wm = wid & 1, wn = wid >> 1;
    const int g = lane >> 2, tig = lane & 3;
    const int bm = blockIdx.y * 128, bn = blockIdx.x * 128;

    // loader: 8 chunks/thread (p: 0=A, 1=B), 1024 chunks/plane
    const __half* gsrc[8]; uint32_t soff[8];
#pragma unroll
    for (int i = 0; i < 8; i++) {
        int p = i >> 2;
        int sub = (i & 3) * 256 + tid;      // 0..1023
        int row = sub >> 3, col = sub & 7;  // 8 chunks per 64-half row
        const __half* base = (p == 0) ? Ah_g + (size_t)bm * DIM : Bh_g + (size_t)bn * DIM;
        gsrc[i] = base + (size_t)row * DIM + col * 8;
        soff[i] = (uint32_t)(p * PLANE_H + row * GLD + col * 8) * 2;
    }

    float acc[4][4][4];
#pragma unroll
    for (int mf = 0; mf < 4; mf++)
#pragma unroll
        for (int nf = 0; nf < 4; nf++)
#pragma unroll
            for (int r = 0; r < 4; r++) acc[mf][nf][r] = 0.0f;

    const uint32_t a_row0 = (uint32_t)(wm * 64 + (lane & 15));
    const uint32_t a_koff = (uint32_t)((lane >> 4) * 8);
    const uint32_t b_row0 = (uint32_t)(wn * 32 + ((lane >> 3) & 1) * 8 + (lane & 7));

    {
#pragma unroll
        for (int i = 0; i < 8; i++) cp16(sbase + soff[i], gsrc[i]);
        CP_COMMIT();
    }

    for (int kt = 0; kt < NKT; kt++) {
        int s = kt & 1;
        if (kt + 1 < NKT) {
            uint32_t sb2 = sbase + (uint32_t)((s ^ 1) * STAGE_H) * 2;
            const int koff = (kt + 1) * BK;
#pragma unroll
            for (int i = 0; i < 8; i++) cp16(sb2 + soff[i], gsrc[i] + koff);
            CP_COMMIT();
            CP_WAIT(1);
        } else {
            CP_WAIT(0);
        }
        __syncthreads();

        const uint32_t st = sbase + (uint32_t)(s * STAGE_H) * 2;
#pragma unroll
        for (int kk = 0; kk < 4; kk++) {
            unsigned ah[4][4];
#pragma unroll
            for (int mf = 0; mf < 4; mf++) {
                uint32_t ra = st + ((a_row0 + mf * 16) * GLD + kk * 16 + a_koff) * 2;
                ldsm4(ah[mf], ra);
            }
#pragma unroll
            for (int g2 = 0; g2 < 2; g2++) {
                uint32_t rb = st + (PLANE_H + (b_row0 + g2 * 16) * GLD + kk * 16 + a_koff) * 2;
                unsigned bh[4];
                ldsm4(bh, rb);
#pragma unroll
                for (int mf = 0; mf < 4; mf++) {
                    mma16816(acc[mf][2*g2],   ah[mf], bh[0], bh[2]);
                    mma16816(acc[mf][2*g2+1], ah[mf], bh[1], bh[3]);
                }
            }
        }
        __syncthreads();
    }

#pragma unroll
    for (int mf = 0; mf < 4; mf++)
#pragma unroll
        for (int nf = 0; nf < 4; nf++) {
            int row = bm + wm * 64 + mf * 16 + g;
            int col = bn + wn * 32 + nf * 8 + 2 * tig;
            float v0 = acc[mf][nf][0] * alpha, v1 = acc[mf][nf][1] * alpha;
            float v2 = acc[mf][nf][2] * alpha, v3 = acc[mf][nf][3] * alpha;
            if (Ch) {
                __half h0,l0,h1,l1,h2,l2,h3,l3;
                split_f32(v0,h0,l0); split_f32(v1,h1,l1);
                split_f32(v2,h2,l2); split_f32(v3,h3,l3);
                *reinterpret_cast<__half2*>(&Ch[(size_t)row*DIM+col])     = __halves2half2(h0,h1);
                *reinterpret_cast<__half2*>(&Ch[(size_t)(row+8)*DIM+col]) = __halves2half2(h2,h3);
                if (Cl) {
                    *reinterpret_cast<__half2*>(&Cl[(size_t)row*DIM+col])     = __halves2half2(l0,l1);
                    *reinterpret_cast<__half2*>(&Cl[(size_t)(row+8)*DIM+col]) = __halves2half2(l2,l3);
                }
            } else {
                *reinterpret_cast<float2*>(&C[(size_t)row*DIM+col])       = make_float2(v0,v1);
                *reinterpret_cast<float2*>(&C[(size_t)(row+8)*DIM+col])   = make_float2(v2,v3);
            }
        }
}

// fused Q/K/V projections: blockIdx.z selects operand set
// Q: hi out. K: hi out. V: hi+lo out (PV 2-term).
__global__ __launch_bounds__(256, 2) void gemm_qkv()
{
    extern __shared__ __half sm[];
    int z = blockIdx.z;
    const __half* A  = (z == 0) ? g_Xqh : g_Xkh;
    const __half* Bh = (z == 0) ? g_Wqh : (z == 1) ? g_Wkh : g_Wvh;
    __half* Ch = (z == 0) ? g_Qh : (z == 1) ? g_Kh : g_Vh;
    __half* Cl = (z == 2) ? g_Vl : (__half*)nullptr;
    float alpha = (z == 0) ? QSCALE : 1.0f;
    gemm_body(A, Bh, nullptr, Ch, Cl, alpha, sm);
}

// output projection: fp32 result
__global__ __launch_bounds__(256, 2) void gemm_o(float* __restrict__ out)
{
    extern __shared__ __half sm[];
    gemm_body(g_Cth, g_Woh, out, nullptr, nullptr, 1.0f, sm);
}

// fused fp32 -> fp16 hi (y=0: xq->Xqh, y=1: xkv->Xkh)
__global__ __launch_bounds__(256) void f32toh2(const float4* __restrict__ Xq, const float4* __restrict__ Xkv){
    const float4* X = blockIdx.y ? Xkv : Xq;
    __half2* H = reinterpret_cast<__half2*>(blockIdx.y ? g_Xkh : g_Xqh);
    int i = blockIdx.x * 256 + threadIdx.x;
    float4 v = X[i];
    H[2*i]   = __halves2half2(__float2half_rn(v.x), __float2half_rn(v.y));
    H[2*i+1] = __halves2half2(__float2half_rn(v.z), __float2half_rn(v.w));
}

// fused weight transpose (hi only): blockIdx.z selects {Wq,Wk,Wv,Wo}
__global__ __launch_bounds__(256) void transpose_h4(
    const float* __restrict__ W0, const float* __restrict__ W1,
    const float* __restrict__ W2, const float* __restrict__ W3)
{
    __shared__ float t[32][33];
    int z = blockIdx.z;
    const float* W = (z == 0) ? W0 : (z == 1) ? W1 : (z == 2) ? W2 : W3;
    __half* TH = (z == 0) ? g_Wqh : (z == 1) ? g_Wkh : (z == 2) ? g_Wvh : g_Woh;
    int x = blockIdx.x*32 + threadIdx.x, y = blockIdx.y*32 + threadIdx.y;
#pragma unroll
    for (int j = 0; j < 4; j++) t[threadIdx.y + j*8][threadIdx.x] = W[(size_t)(y + j*8)*DIM + x];
    __syncthreads();
    int x2 = blockIdx.y*32 + threadIdx.x, y2 = blockIdx.x*32 + threadIdx.y;
#pragma unroll
    for (int j = 0; j < 4; j++) {
        TH[(size_t)(y2 + j*8)*DIM + x2] = __float2half_rn(t[threadIdx.x][threadIdx.y + j*8]);
    }
}

// =====================================================================
// flash2: FA-2. S = Qh*Kh (1-term). PV = P-hi*(Vh+Vl) (2-term). (unchanged)
// 3 planes/stage {Kh,Vh,Vl} = 48KB; 2 stages = 96KB smem.
// =====================================================================
#define FSTG 49152

__global__ __launch_bounds__(256) void flash2()
{
    extern __shared__ char fs[];
    const uint32_t sb = smem_u32(fs);
    const int tid = threadIdx.x, lane = tid & 31, wid = tid >> 5;
    const int g = lane >> 2, tig = lane & 3;
    const int b = blockIdx.z, h = blockIdx.y, qt = blockIdx.x;
    const int t8 = lane >> 3, l7 = lane & 7;

    const size_t qrow0 = (size_t)(b * SEQ + qt * 128);
    const __half* Qg = g_Qh + qrow0 * DIM + h * HD;
    const size_t kvbase = (size_t)b * SEQ * DIM + h * HD;

    const __half* ksrc[12]; uint32_t kdst[12];
#pragma unroll
    for (int i = 0; i < 12; i++) {
        int p = i >> 2;
        int m = tid + 256 * (i & 3);
        int r = m >> 4, c = m & 15;
        const __half* base =
            (p == 0) ? g_Kh + kvbase : (p == 1) ? g_Vh + kvbase : g_Vl + kvbase;
        ksrc[i] = base + (size_t)r * DIM + c * 8;
        kdst[i] = (uint32_t)(p * 16384 + r * 256 + ((c ^ (r & 7)) << 4));
    }

#pragma unroll
    for (int i = 0; i < 8; i++) {
        int n = tid + 256 * i;
        int r = n >> 4, c = n & 15;
        cp16(sb + FSTG + r * 256 + ((c ^ (r & 7)) << 4), Qg + (size_t)r * DIM + c * 8);
    }
    CP_COMMIT();
#pragma unroll
    for (int i = 0; i < 12; i++) cp16(sb + kdst[i], ksrc[i]);
    CP_COMMIT();

    CP_WAIT(1);
    __syncthreads();

    unsigned q[8][4];
#pragma unroll
    for (int kk = 0; kk < 8; kk++) {
        uint32_t row = (uint32_t)(wid * 16 + ((t8 & 1) << 3) + l7);
        uint32_t kc  = (uint32_t)(2 * kk + (t8 >> 1));
        ldsm4(q[kk], sb + FSTG + row * 256 + ((kc ^ (row & 7)) << 4));
    }
    __syncthreads();

    float o[16][4];
#pragma unroll
    for (int i = 0; i < 16; i++) { o[i][0]=o[i][1]=o[i][2]=o[i][3]=0.0f; }
    float m0 = -1e30f, m1 = -1e30f, l0 = 0.0f, l1 = 0.0f;

    for (int kt = 0; kt < SEQ / 64; kt++) {
        int s = kt & 1;
        if (kt + 1 < SEQ / 64) {
            uint32_t dst = sb + (uint32_t)((s ^ 1) * FSTG);
            size_t koff = (size_t)(kt + 1) * 64 * DIM;
#pragma unroll
            for (int i = 0; i < 12; i++) cp16(dst + kdst[i], ksrc[i] + koff);
            CP_COMMIT();
            CP_WAIT(1);
        } else {
            CP_WAIT(0);
        }
        __syncthreads();
        const uint32_t st = sb + (uint32_t)(s * FSTG);

        float sc[8][4];
#pragma unroll
        for (int nf = 0; nf < 8; nf++) { sc[nf][0]=sc[nf][1]=sc[nf][2]=sc[nf][3]=0.0f; }
#pragma unroll
        for (int kk = 0; kk < 8; kk++) {
#pragma unroll
            for (int nb = 0; nb < 4; nb++) {
                uint32_t n  = (uint32_t)(nb * 16 + ((t8 >> 1) << 3) + l7);
                uint32_t kc = (uint32_t)(2 * kk + (t8 & 1));
                uint32_t ak = st + n * 256 + ((kc ^ (n & 7)) << 4);
                unsigned bh[4];
                ldsm4(bh, ak);
                mma16816(sc[2*nb],   q[kk], bh[0], bh[1]);
                mma16816(sc[2*nb+1], q[kk], bh[2], bh[3]);
            }
        }

        float r0 = -1e30f, r1 = -1e30f;
#pragma unroll
        for (int nf = 0; nf < 8; nf++) { r0 = fmaxf(r0, fmaxf(sc[nf][0], sc[nf][1])); r1 = fmaxf(r1, fmaxf(sc[nf][2], sc[nf][3])); }
        r0 = fmaxf(r0, __shfl_xor_sync(~0u, r0, 1)); r0 = fmaxf(r0, __shfl_xor_sync(~0u, r0, 2));
        r1 = fmaxf(r1, __shfl_xor_sync(~0u, r1, 1)); r1 = fmaxf(r1, __shfl_xor_sync(~0u, r1, 2));
        float mn0 = fmaxf(m0, r0), mn1 = fmaxf(m1, r1);
        float f0 = __expf(m0 - mn0), f1 = __expf(m1 - mn1);
        m0 = mn0; m1 = mn1;
        float rs0 = 0.0f, rs1 = 0.0f;
#pragma unroll
        for (int nf = 0; nf < 8; nf++) {
            sc[nf][0] = __expf(sc[nf][0] - m0); sc[nf][1] = __expf(sc[nf][1] - m0);
            sc[nf][2] = __expf(sc[nf][2] - m1); sc[nf][3] = __expf(sc[nf][3] - m1);
            rs0 += sc[nf][0] + sc[nf][1]; rs1 += sc[nf][2] + sc[nf][3];
        }
        rs0 += __shfl_xor_sync(~0u, rs0, 1); rs0 += __shfl_xor_sync(~0u, rs0, 2);
        rs1 += __shfl_xor_sync(~0u, rs1, 1); rs1 += __shfl_xor_sync(~0u, rs1, 2);
        l0 = l0 * f0 + rs0; l1 = l1 * f1 + rs1;
#pragma unroll
        for (int nf = 0; nf < 16; nf++) { o[nf][0] *= f0; o[nf][1] *= f0; o[nf][2] *= f1; o[nf][3] *= f1; }

#pragma unroll
        for (int kk2 = 0; kk2 < 4; kk2++) {
            const int j0 = 2*kk2, j1 = 2*kk2 + 1;
            unsigned ah_[4] = {
                pack_h2(__float2half_rn(sc[j0][0]), __float2half_rn(sc[j0][1])),
                pack_h2(__float2half_rn(sc[j0][2]), __float2half_rn(sc[j0][3])),
                pack_h2(__float2half_rn(sc[j1][0]), __float2half_rn(sc[j1][1])),
                pack_h2(__float2half_rn(sc[j1][2]), __float2half_rn(sc[j1][3]))};
            uint32_t kr = (uint32_t)(kk2 * 16 + ((t8 & 1) << 3) + l7);
            uint32_t vrow = st + 16384 + kr * 256;
            uint32_t sw7 = (kr & 7);
#pragma unroll
            for (int na = 0; na < 8; na++) {
                uint32_t nblk = (uint32_t)(2 * na + (t8 >> 1));
                uint32_t av = vrow + ((nblk ^ sw7) << 4);
                unsigned vh[4], vl[4];
                ldsm4t(vh, av);
                ldsm4t(vl, av + 16384);
                mma16816(o[2*na],   ah_, vh[0], vh[1]);
                mma16816(o[2*na+1], ah_, vh[2], vh[3]);
                mma16816(o[2*na],   ah_, vl[0], vl[1]);
                mma16816(o[2*na+1], ah_, vl[2], vl[3]);
            }
        }
        __syncthreads();
    }

    float i0 = 1.0f / l0, i1 = 1.0f / l1;
    const size_t row = qrow0 + wid * 16 + g;
    __half* Ch = g_Cth + row * DIM + h * HD;
#pragma unroll
    for (int nf2 = 0; nf2 < 16; nf2++) {
        int c = nf2 * 8 + 2 * tig;
        float v0 = o[nf2][0] * i0, v1 = o[nf2][1] * i0;
        float v2 = o[nf2][2] * i1, v3 = o[nf2][3] * i1;
        *reinterpret_cast<__half2*>(Ch + c)         = __halves2half2(__float2half_rn(v0), __float2half_rn(v1));
        *reinterpret_cast<__half2*>(Ch + 8*DIM + c) = __halves2half2(__float2half_rn(v2), __float2half_rn(v3));
    }
}

// =====================================================================
extern "C" void kernel_launch(void* const* d_in, const int* in_sizes, int n_in,
                              void* d_out, int out_size)
{
    const float* xq  = (const float*)d_in[0];
    const float* xkv = (const float*)d_in[1];
    const float* Wq  = (const float*)d_in[2];
    const float* Wk  = (const float*)d_in[3];
    const float* Wv  = (const float*)d_in[4];
    const float* Wo  = (const float*)d_in[5];
    float* out = (float*)d_out;

    int nb = (MROWS * DIM / 4) / 256;
    f32toh2<<<dim3(nb, 2), 256>>>((const float4*)xq, (const float4*)xkv);
    transpose_h4<<<dim3(DIM/32, DIM/32, 4), dim3(32, 8)>>>(Wq, Wk, Wv, Wo);

    cudaFuncSetAttribute(gemm_qkv, cudaFuncAttributeMaxDynamicSharedMemorySize, GEMM_SMEM);
    cudaFuncSetAttribute(gemm_o,   cudaFuncAttributeMaxDynamicSharedMemorySize, GEMM_SMEM);
    gemm_qkv<<<dim3(DIM/128, MROWS/128, 3), 256, GEMM_SMEM>>>();

    cudaFuncSetAttribute(flash2, cudaFuncAttributeMaxDynamicSharedMemorySize, 2 * FSTG);
    flash2<<<dim3(SEQ/128, HEADS, BATCH), 256, 2 * FSTG>>>();

    gemm_o<<<dim3(DIM/128, MROWS/128), 256, GEMM_SMEM>>>(out);
}

// round 14
// speedup vs baseline: 2.0160x; 1.0946x over previous
#include <cuda_runtime.h>
#include <cuda_fp16.h>
#include <cstdint>
#include <math.h>

#define BATCH 8
#define SEQ   1024
#define DIM   2048
#define HEADS 16
#define HD    128
#define MROWS (BATCH*SEQ)
#define QSCALE 0.08838834764831845f

// ---- scratch (device globals) ----
__device__ __align__(256) __half g_Qh[MROWS*DIM];
__device__ __align__(256) __half g_Kh[MROWS*DIM];
__device__ __align__(256) __half g_Vh[MROWS*DIM];
__device__ __align__(256) __half g_Cth[MROWS*DIM];
__device__ __align__(256) __half g_Xqh[MROWS*DIM];
__device__ __align__(256) __half g_Xkh[MROWS*DIM];
__device__ __align__(256) __half g_Wqh[DIM*DIM];
__device__ __align__(256) __half g_Wkh[DIM*DIM];
__device__ __align__(256) __half g_Wvh[DIM*DIM];
__device__ __align__(256) __half g_Woh[DIM*DIM];

// ---- helpers ----
__device__ __forceinline__ unsigned pack_h2(__half a, __half b){ __half2 h=__halves2half2(a,b); return *reinterpret_cast<unsigned*>(&h); }
__device__ __forceinline__ void split_f32(float x, __half& hi, __half& lo){ hi=__float2half_rn(x); lo=__float2half_rn(x-__half2float(hi)); }
__device__ __forceinline__ void mma16816(float* c, const unsigned* a, unsigned b0, unsigned b1){
    asm volatile("mma.sync.aligned.m16n8k16.row.col.f32.f16.f16.f32 {%0,%1,%2,%3},{%4,%5,%6,%7},{%8,%9},{%0,%1,%2,%3};\n"
        : "+f"(c[0]),"+f"(c[1]),"+f"(c[2]),"+f"(c[3]) : "r"(a[0]),"r"(a[1]),"r"(a[2]),"r"(a[3]),"r"(b0),"r"(b1));
}
__device__ __forceinline__ uint32_t smem_u32(const void* p){ uint32_t a; asm("{ .reg .u64 t; cvta.to.shared.u64 t, %1; cvt.u32.u64 %0, t; }":"=r"(a):"l"(p)); return a; }
__device__ __forceinline__ void cp16(uint32_t s, const void* g){ asm volatile("cp.async.cg.shared.global [%0], [%1], 16;"::"r"(s),"l"(g)); }
__device__ __forceinline__ void ldsm4(unsigned* r, uint32_t addr){
    asm volatile("ldmatrix.sync.aligned.m8n8.x4.shared.b16 {%0,%1,%2,%3}, [%4];"
        : "=r"(r[0]),"=r"(r[1]),"=r"(r[2]),"=r"(r[3]) : "r"(addr));
}
__device__ __forceinline__ void ldsm4t(unsigned* r, uint32_t addr){
    asm volatile("ldmatrix.sync.aligned.m8n8.x4.trans.shared.b16 {%0,%1,%2,%3}, [%4];"
        : "=r"(r[0]),"=r"(r[1]),"=r"(r[2]),"=r"(r[3]) : "r"(addr));
}
#define CP_COMMIT() asm volatile("cp.async.commit_group;" ::: "memory")
#define CP_WAIT(n)  asm volatile("cp.async.wait_group %0;" :: "n"(n) : "memory")

// =====================================================================
// HMMA 1-term GEMM: C = alpha * Ah @ Bh^T  (unchanged from round 13)
// CTA 128x128, warp tile 64x32, BK=64 (32 ktiles), 2-stage cp.async.
// =====================================================================
#define BK 64
#define GLD 72
#define PLANE_H (128*GLD)
#define STAGE_H (2*PLANE_H)
#define GEMM_SMEM (2*STAGE_H*2)   // 73728 B
#define NKT (DIM/BK)

__device__ __forceinline__ void gemm_body(
    const __half* __restrict__ Ah_g, const __half* __restrict__ Bh_g,
    float* __restrict__ C, __half* __restrict__ Ch, __half* __restrict__ Cl,
    float alpha, __half* sm)
{
    const uint32_t sbase = smem_u32(sm);
    const int tid = threadIdx.x, lane = tid & 31, wid = tid >> 5;
    const int wm = wid & 1, wn = wid >> 1;
    const int g = lane >> 2, tig = lane & 3;
    const int bm = blockIdx.y * 128, bn = blockIdx.x * 128;

    const __half* gsrc[8]; uint32_t soff[8];
#pragma unroll
    for (int i = 0; i < 8; i++) {
        int p = i >> 2;
        int sub = (i & 3) * 256 + tid;
        int row = sub >> 3, col = sub & 7;
        const __half* base = (p == 0) ? Ah_g + (size_t)bm * DIM : Bh_g + (size_t)bn * DIM;
        gsrc[i] = base + (size_t)row * DIM + col * 8;
        soff[i] = (uint32_t)(p * PLANE_H + row * GLD + col * 8) * 2;
    }

    float acc[4][4][4];
#pragma unroll
    for (int mf = 0; mf < 4; mf++)
#pragma unroll
        for (int nf = 0; nf < 4; nf++)
#pragma unroll
            for (int r = 0; r < 4; r++) acc[mf][nf][r] = 0.0f;

    const uint32_t a_row0 = (uint32_t)(wm * 64 + (lane & 15));
    const uint32_t a_koff = (uint32_t)((lane >> 4) * 8);
    const uint32_t b_row0 = (uint32_t)(wn * 32 + ((lane >> 3) & 1) * 8 + (lane & 7));

    {
#pragma unroll
        for (int i = 0; i < 8; i++) cp16(sbase + soff[i], gsrc[i]);
        CP_COMMIT();
    }

    for (int kt = 0; kt < NKT; kt++) {
        int s = kt & 1;
        if (kt + 1 < NKT) {
            uint32_t sb2 = sbase + (uint32_t)((s ^ 1) * STAGE_H) * 2;
            const int koff = (kt + 1) * BK;
#pragma unroll
            for (int i = 0; i < 8; i++) cp16(sb2 + soff[i], gsrc[i] + koff);
            CP_COMMIT();
            CP_WAIT(1);
        } else {
            CP_WAIT(0);
        }
        __syncthreads();

        const uint32_t st = sbase + (uint32_t)(s * STAGE_H) * 2;
#pragma unroll
        for (int kk = 0; kk < 4; kk++) {
            unsigned ah[4][4];
#pragma unroll
            for (int mf = 0; mf < 4; mf++) {
                uint32_t ra = st + ((a_row0 + mf * 16) * GLD + kk * 16 + a_koff) * 2;
                ldsm4(ah[mf], ra);
            }
#pragma unroll
            for (int g2 = 0; g2 < 2; g2++) {
                uint32_t rb = st + (PLANE_H + (b_row0 + g2 * 16) * GLD + kk * 16 + a_koff) * 2;
                unsigned bh[4];
                ldsm4(bh, rb);
#pragma unroll
                for (int mf = 0; mf < 4; mf++) {
                    mma16816(acc[mf][2*g2],   ah[mf], bh[0], bh[2]);
                    mma16816(acc[mf][2*g2+1], ah[mf], bh[1], bh[3]);
                }
            }
        }
        __syncthreads();
    }

#pragma unroll
    for (int mf = 0; mf < 4; mf++)
#pragma unroll
        for (int nf = 0; nf < 4; nf++) {
            int row = bm + wm * 64 + mf * 16 + g;
            int col = bn + wn * 32 + nf * 8 + 2 * tig;
            float v0 = acc[mf][nf][0] * alpha, v1 = acc[mf][nf][1] * alpha;
            float v2 = acc[mf][nf][2] * alpha, v3 = acc[mf][nf][3] * alpha;
            if (Ch) {
                *reinterpret_cast<__half2*>(&Ch[(size_t)row*DIM+col])     = __halves2half2(__float2half_rn(v0), __float2half_rn(v1));
                *reinterpret_cast<__half2*>(&Ch[(size_t)(row+8)*DIM+col]) = __halves2half2(__float2half_rn(v2), __float2half_rn(v3));
                if (Cl) {
                    __half h0,l0,h1,l1,h2,l2,h3,l3;
                    split_f32(v0,h0,l0); split_f32(v1,h1,l1);
                    split_f32(v2,h2,l2); split_f32(v3,h3,l3);
                    *reinterpret_cast<__half2*>(&Cl[(size_t)row*DIM+col])     = __halves2half2(l0,l1);
                    *reinterpret_cast<__half2*>(&Cl[(size_t)(row+8)*DIM+col]) = __halves2half2(l2,l3);
                }
            } else {
                *reinterpret_cast<float2*>(&C[(size_t)row*DIM+col])       = make_float2(v0,v1);
                *reinterpret_cast<float2*>(&C[(size_t)(row+8)*DIM+col])   = make_float2(v2,v3);
            }
        }
}

// fused Q/K/V projections: blockIdx.z selects operand set (all hi-only out)
__global__ __launch_bounds__(256, 2) void gemm_qkv()
{
    extern __shared__ __half sm[];
    int z = blockIdx.z;
    const __half* A  = (z == 0) ? g_Xqh : g_Xkh;
    const __half* Bh = (z == 0) ? g_Wqh : (z == 1) ? g_Wkh : g_Wvh;
    __half* Ch = (z == 0) ? g_Qh : (z == 1) ? g_Kh : g_Vh;
    float alpha = (z == 0) ? QSCALE : 1.0f;
    gemm_body(A, Bh, nullptr, Ch, nullptr, alpha, sm);
}

// output projection: fp32 result
__global__ __launch_bounds__(256, 2) void gemm_o(float* __restrict__ out)
{
    extern __shared__ __half sm[];
    gemm_body(g_Cth, g_Woh, out, nullptr, nullptr, 1.0f, sm);
}

// fused fp32 -> fp16 hi (y=0: xq->Xqh, y=1: xkv->Xkh)
__global__ __launch_bounds__(256) void f32toh2(const float4* __restrict__ Xq, const float4* __restrict__ Xkv){
    const float4* X = blockIdx.y ? Xkv : Xq;
    __half2* H = reinterpret_cast<__half2*>(blockIdx.y ? g_Xkh : g_Xqh);
    int i = blockIdx.x * 256 + threadIdx.x;
    float4 v = X[i];
    H[2*i]   = __halves2half2(__float2half_rn(v.x), __float2half_rn(v.y));
    H[2*i+1] = __halves2half2(__float2half_rn(v.z), __float2half_rn(v.w));
}

// fused weight transpose (hi only): blockIdx.z selects {Wq,Wk,Wv,Wo}
__global__ __launch_bounds__(256) void transpose_h4(
    const float* __restrict__ W0, const float* __restrict__ W1,
    const float* __restrict__ W2, const float* __restrict__ W3)
{
    __shared__ float t[32][33];
    int z = blockIdx.z;
    const float* W = (z == 0) ? W0 : (z == 1) ? W1 : (z == 2) ? W2 : W3;
    __half* TH = (z == 0) ? g_Wqh : (z == 1) ? g_Wkh : (z == 2) ? g_Wvh : g_Woh;
    int x = blockIdx.x*32 + threadIdx.x, y = blockIdx.y*32 + threadIdx.y;
#pragma unroll
    for (int j = 0; j < 4; j++) t[threadIdx.y + j*8][threadIdx.x] = W[(size_t)(y + j*8)*DIM + x];
    __syncthreads();
    int x2 = blockIdx.y*32 + threadIdx.x, y2 = blockIdx.x*32 + threadIdx.y;
#pragma unroll
    for (int j = 0; j < 4; j++) {
        TH[(size_t)(y2 + j*8)*DIM + x2] = __float2half_rn(t[threadIdx.x][threadIdx.y + j*8]);
    }
}

// =====================================================================
// flash2: FA-2. S = Qh*Kh (1-term). PV = P-hi*Vh (1-term). KT=128.
// 2 planes/stage {Kh, Vh} = 64KB; 2 stages = 128KB smem. 8 ktiles.
// =====================================================================
#define FSTG 65536

__global__ __launch_bounds__(256) void flash2()
{
    extern __shared__ char fs[];
    const uint32_t sb = smem_u32(fs);
    const int tid = threadIdx.x, lane = tid & 31, wid = tid >> 5;
    const int g = lane >> 2, tig = lane & 3;
    const int b = blockIdx.z, h = blockIdx.y, qt = blockIdx.x;
    const int t8 = lane >> 3, l7 = lane & 7;

    const size_t qrow0 = (size_t)(b * SEQ + qt * 128);
    const __half* Qg = g_Qh + qrow0 * DIM + h * HD;
    const size_t kvbase = (size_t)b * SEQ * DIM + h * HD;

    // loader: 16 chunks/thread per stage (p: 0=Kh, 1=Vh; 128 rows each)
    const __half* ksrc[16]; uint32_t kdst[16];
#pragma unroll
    for (int i = 0; i < 16; i++) {
        int p = i >> 3;
        int m = tid + 256 * (i & 7);        // 0..2047
        int r = m >> 4, c = m & 15;
        const __half* base = (p == 0) ? g_Kh + kvbase : g_Vh + kvbase;
        ksrc[i] = base + (size_t)r * DIM + c * 8;
        kdst[i] = (uint32_t)(p * 32768 + r * 256 + ((c ^ (r & 7)) << 4));
    }

    // prime: Q into stage-1 area, then KV stage 0
#pragma unroll
    for (int i = 0; i < 8; i++) {
        int n = tid + 256 * i;
        int r = n >> 4, c = n & 15;
        cp16(sb + FSTG + r * 256 + ((c ^ (r & 7)) << 4), Qg + (size_t)r * DIM + c * 8);
    }
    CP_COMMIT();
#pragma unroll
    for (int i = 0; i < 16; i++) cp16(sb + kdst[i], ksrc[i]);
    CP_COMMIT();

    CP_WAIT(1);
    __syncthreads();

    unsigned q[8][4];
#pragma unroll
    for (int kk = 0; kk < 8; kk++) {
        uint32_t row = (uint32_t)(wid * 16 + ((t8 & 1) << 3) + l7);
        uint32_t kc  = (uint32_t)(2 * kk + (t8 >> 1));
        ldsm4(q[kk], sb + FSTG + row * 256 + ((kc ^ (row & 7)) << 4));
    }
    __syncthreads();   // all warps consumed Q; stage-1 area reusable

    float o[16][4];
#pragma unroll
    for (int i = 0; i < 16; i++) { o[i][0]=o[i][1]=o[i][2]=o[i][3]=0.0f; }
    float m0 = -1e30f, m1 = -1e30f, l0 = 0.0f, l1 = 0.0f;

    for (int kt = 0; kt < SEQ / 128; kt++) {
        int s = kt & 1;
        if (kt + 1 < SEQ / 128) {
            uint32_t dst = sb + (uint32_t)((s ^ 1) * FSTG);
            size_t koff = (size_t)(kt + 1) * 128 * DIM;
#pragma unroll
            for (int i = 0; i < 16; i++) cp16(dst + kdst[i], ksrc[i] + koff);
            CP_COMMIT();
            CP_WAIT(1);
        } else {
            CP_WAIT(0);
        }
        __syncthreads();
        const uint32_t st = sb + (uint32_t)(s * FSTG);

        // ---- S = Qh*Kh  (16x128 per warp) ----
        float sc[16][4];
#pragma unroll
        for (int nf = 0; nf < 16; nf++) { sc[nf][0]=sc[nf][1]=sc[nf][2]=sc[nf][3]=0.0f; }
#pragma unroll
        for (int kk = 0; kk < 8; kk++) {
#pragma unroll
            for (int nb = 0; nb < 8; nb++) {
                uint32_t n  = (uint32_t)(nb * 16 + ((t8 >> 1) << 3) + l7);
                uint32_t kc = (uint32_t)(2 * kk + (t8 & 1));
                uint32_t ak = st + n * 256 + ((kc ^ (n & 7)) << 4);
                unsigned bh[4];
                ldsm4(bh, ak);
                mma16816(sc[2*nb],   q[kk], bh[0], bh[1]);
                mma16816(sc[2*nb+1], q[kk], bh[2], bh[3]);
            }
        }

        // ---- online softmax ----
        float r0 = -1e30f, r1 = -1e30f;
#pragma unroll
        for (int nf = 0; nf < 16; nf++) { r0 = fmaxf(r0, fmaxf(sc[nf][0], sc[nf][1])); r1 = fmaxf(r1, fmaxf(sc[nf][2], sc[nf][3])); }
        r0 = fmaxf(r0, __shfl_xor_sync(~0u, r0, 1)); r0 = fmaxf(r0, __shfl_xor_sync(~0u, r0, 2));
        r1 = fmaxf(r1, __shfl_xor_sync(~0u, r1, 1)); r1 = fmaxf(r1, __shfl_xor_sync(~0u, r1, 2));
        float mn0 = fmaxf(m0, r0), mn1 = fmaxf(m1, r1);
        float f0 = __expf(m0 - mn0), f1 = __expf(m1 - mn1);
        m0 = mn0; m1 = mn1;
        float rs0 = 0.0f, rs1 = 0.0f;
#pragma unroll
        for (int nf = 0; nf < 16; nf++) {
            sc[nf][0] = __expf(sc[nf][0] - m0); sc[nf][1] = __expf(sc[nf][1] - m0);
            sc[nf][2] = __expf(sc[nf][2] - m1); sc[nf][3] = __expf(sc[nf][3] - m1);
            rs0 += sc[nf][0] + sc[nf][1]; rs1 += sc[nf][2] + sc[nf][3];
        }
        rs0 += __shfl_xor_sync(~0u, rs0, 1); rs0 += __shfl_xor_sync(~0u, rs0, 2);
        rs1 += __shfl_xor_sync(~0u, rs1, 1); rs1 += __shfl_xor_sync(~0u, rs1, 2);
        l0 = l0 * f0 + rs0; l1 = l1 * f1 + rs1;
#pragma unroll
        for (int nf = 0; nf < 16; nf++) { o[nf][0] *= f0; o[nf][1] *= f0; o[nf][2] *= f1; o[nf][3] *= f1; }

        // ---- O += P-hi @ Vh  (kv dim 128) ----
#pragma unroll
        for (int kk2 = 0; kk2 < 8; kk2++) {
            const int j0 = 2*kk2, j1 = 2*kk2 + 1;
            unsigned ah_[4] = {
                pack_h2(__float2half_rn(sc[j0][0]), __float2half_rn(sc[j0][1])),
                pack_h2(__float2half_rn(sc[j0][2]), __float2half_rn(sc[j0][3])),
                pack_h2(__float2half_rn(sc[j1][0]), __float2half_rn(sc[j1][1])),
                pack_h2(__float2half_rn(sc[j1][2]), __float2half_rn(sc[j1][3]))};
            uint32_t kr = (uint32_t)(kk2 * 16 + ((t8 & 1) << 3) + l7);
            uint32_t vrow = st + 32768 + kr * 256;
            uint32_t sw7 = (kr & 7);
#pragma unroll
            for (int na = 0; na < 8; na++) {
                uint32_t nblk = (uint32_t)(2 * na + (t8 >> 1));
                uint32_t av = vrow + ((nblk ^ sw7) << 4);
                unsigned vh[4];
                ldsm4t(vh, av);
                mma16816(o[2*na],   ah_, vh[0], vh[1]);
                mma16816(o[2*na+1], ah_, vh[2], vh[3]);
            }
        }
        __syncthreads();
    }

    // epilogue: ctx = O/l -> hi plane
    float i0 = 1.0f / l0, i1 = 1.0f / l1;
    const size_t row = qrow0 + wid * 16 + g;
    __half* Ch = g_Cth + row * DIM + h * HD;
#pragma unroll
    for (int nf2 = 0; nf2 < 16; nf2++) {
        int c = nf2 * 8 + 2 * tig;
        float v0 = o[nf2][0] * i0, v1 = o[nf2][1] * i0;
        float v2 = o[nf2][2] * i1, v3 = o[nf2][3] * i1;
        *reinterpret_cast<__half2*>(Ch + c)         = __halves2half2(__float2half_rn(v0), __float2half_rn(v1));
        *reinterpret_cast<__half2*>(Ch + 8*DIM + c) = __halves2half2(__float2half_rn(v2), __float2half_rn(v3));
    }
}

// =====================================================================
extern "C" void kernel_launch(void* const* d_in, const int* in_sizes, int n_in,
                              void* d_out, int out_size)
{
    const float* xq  = (const float*)d_in[0];
    const float* xkv = (const float*)d_in[1];
    const float* Wq  = (const float*)d_in[2];
    const float* Wk  = (const float*)d_in[3];
    const float* Wv  = (const float*)d_in[4];
    const float* Wo  = (const float*)d_in[5];
    float* out = (float*)d_out;

    int nb = (MROWS * DIM / 4) / 256;
    f32toh2<<<dim3(nb, 2), 256>>>((const float4*)xq, (const float4*)xkv);
    transpose_h4<<<dim3(DIM/32, DIM/32, 4), dim3(32, 8)>>>(Wq, Wk, Wv, Wo);

    cudaFuncSetAttribute(gemm_qkv, cudaFuncAttributeMaxDynamicSharedMemorySize, GEMM_SMEM);
    cudaFuncSetAttribute(gemm_o,   cudaFuncAttributeMaxDynamicSharedMemorySize, GEMM_SMEM);
    gemm_qkv<<<dim3(DIM/128, MROWS/128, 3), 256, GEMM_SMEM>>>();

    cudaFuncSetAttribute(flash2, cudaFuncAttributeMaxDynamicSharedMemorySize, 2 * FSTG);
    flash2<<<dim3(SEQ/128, HEADS, BATCH), 256, 2 * FSTG>>>();

    gemm_o<<<dim3(DIM/128, MROWS/128), 256, GEMM_SMEM>>>(out);
}

// round 15
// speedup vs baseline: 2.4062x; 1.1935x over previous
#include <cuda_runtime.h>
#include <cuda_fp16.h>
#include <cstdint>
#include <math.h>

#define BATCH 8
#define SEQ   1024
#define DIM   2048
#define HEADS 16
#define HD    128
#define MROWS (BATCH*SEQ)
#define QSCALE 0.08838834764831845f

// ---- scratch (device globals) ----
__device__ __align__(256) __half g_Qh[MROWS*DIM];
__device__ __align__(256) __half g_Kh[MROWS*DIM];
__device__ __align__(256) __half g_Vh[MROWS*DIM];
__device__ __align__(256) __half g_Cth[MROWS*DIM];
__device__ __align__(256) __half g_Xqh[MROWS*DIM];
__device__ __align__(256) __half g_Xkh[MROWS*DIM];
// weights in NATURAL [K,N] layout, fp16 (no transpose)
__device__ __align__(256) __half g_Wqh[DIM*DIM];
__device__ __align__(256) __half g_Wkh[DIM*DIM];
__device__ __align__(256) __half g_Wvh[DIM*DIM];
__device__ __align__(256) __half g_Woh[DIM*DIM];

// ---- helpers ----
__device__ __forceinline__ unsigned pack_h2(__half a, __half b){ __half2 h=__halves2half2(a,b); return *reinterpret_cast<unsigned*>(&h); }
__device__ __forceinline__ void mma16816(float* c, const unsigned* a, unsigned b0, unsigned b1){
    asm volatile("mma.sync.aligned.m16n8k16.row.col.f32.f16.f16.f32 {%0,%1,%2,%3},{%4,%5,%6,%7},{%8,%9},{%0,%1,%2,%3};\n"
        : "+f"(c[0]),"+f"(c[1]),"+f"(c[2]),"+f"(c[3]) : "r"(a[0]),"r"(a[1]),"r"(a[2]),"r"(a[3]),"r"(b0),"r"(b1));
}
__device__ __forceinline__ uint32_t smem_u32(const void* p){ uint32_t a; asm("{ .reg .u64 t; cvta.to.shared.u64 t, %1; cvt.u32.u64 %0, t; }":"=r"(a):"l"(p)); return a; }
__device__ __forceinline__ void cp16(uint32_t s, const void* g){ asm volatile("cp.async.cg.shared.global [%0], [%1], 16;"::"r"(s),"l"(g)); }
__device__ __forceinline__ void ldsm4(unsigned* r, uint32_t addr){
    asm volatile("ldmatrix.sync.aligned.m8n8.x4.shared.b16 {%0,%1,%2,%3}, [%4];"
        : "=r"(r[0]),"=r"(r[1]),"=r"(r[2]),"=r"(r[3]) : "r"(addr));
}
__device__ __forceinline__ void ldsm4t(unsigned* r, uint32_t addr){
    asm volatile("ldmatrix.sync.aligned.m8n8.x4.trans.shared.b16 {%0,%1,%2,%3}, [%4];"
        : "=r"(r[0]),"=r"(r[1]),"=r"(r[2]),"=r"(r[3]) : "r"(addr));
}
#define CP_COMMIT() asm volatile("cp.async.commit_group;" ::: "memory")
#define CP_WAIT(n)  asm volatile("cp.async.wait_group %0;" :: "n"(n) : "memory")

// =====================================================================
// HMMA 1-term GEMM: C = alpha * Ah @ W  (W natural [K,N] fp16)
// CTA 128x128, warp tile 64x32, BK=64, 2-stage cp.async.
// A: GLD-padded rows + ldsm4. B: 256B k-rows + XOR swizzle + ldsm4t
// (flash-PV-proven pattern) — no weight transpose needed anywhere.
// =====================================================================
#define BK 64
#define GLD 72
#define APLANE_B (128*GLD*2)          // 18432 B
#define BPLANE_B (64*256)             // 16384 B
#define STAGE_B (APLANE_B + BPLANE_B) // 34816 B
#define GEMM_SMEM (2*STAGE_B)         // 69632 B
#define NKT (DIM/BK)

__device__ __forceinline__ void gemm_body(
    const __half* __restrict__ Ah_g, const __half* __restrict__ Bn_g,
    float* __restrict__ C, __half* __restrict__ Ch,
    float alpha, __half* sm)
{
    const uint32_t sbase = smem_u32(sm);
    const int tid = threadIdx.x, lane = tid & 31, wid = tid >> 5;
    const int wm = wid & 1, wn = wid >> 1;
    const int g = lane >> 2, tig = lane & 3;
    const int t8 = lane >> 3, l7 = lane & 7;
    const int bm = blockIdx.y * 128, bn = blockIdx.x * 128;

    // loader: 8 chunks/thread (i<4: A plane, i>=4: B plane)
    const __half* gsrc[8]; uint32_t soff[8]; int kstep[8];
#pragma unroll
    for (int i = 0; i < 8; i++) {
        if (i < 4) {
            int sub = i * 256 + tid;            // 0..1023
            int row = sub >> 3, col = sub & 7;  // 128 rows x 8 chunks
            gsrc[i] = Ah_g + (size_t)(bm + row) * DIM + col * 8;
            soff[i] = (uint32_t)(row * GLD + col * 8) * 2;
            kstep[i] = BK;
        } else {
            int sub = (i - 4) * 256 + tid;      // 0..1023
            int r = sub >> 4, c = sub & 15;     // 64 k-rows x 16 chunks
            gsrc[i] = Bn_g + (size_t)r * DIM + bn + c * 8;
            soff[i] = (uint32_t)(APLANE_B + r * 256 + ((c ^ (r & 7)) << 4));
            kstep[i] = BK * DIM;
        }
    }

    float acc[4][4][4];
#pragma unroll
    for (int mf = 0; mf < 4; mf++)
#pragma unroll
        for (int nf = 0; nf < 4; nf++)
#pragma unroll
            for (int r = 0; r < 4; r++) acc[mf][nf][r] = 0.0f;

    const uint32_t a_row0 = (uint32_t)(wm * 64 + (lane & 15));
    const uint32_t a_koff = (uint32_t)((lane >> 4) * 8);

    {
#pragma unroll
        for (int i = 0; i < 8; i++) cp16(sbase + soff[i], gsrc[i]);
        CP_COMMIT();
    }

    for (int kt = 0; kt < NKT; kt++) {
        int s = kt & 1;
        if (kt + 1 < NKT) {
            uint32_t sb2 = sbase + (uint32_t)((s ^ 1) * STAGE_B);
#pragma unroll
            for (int i = 0; i < 8; i++) cp16(sb2 + soff[i], gsrc[i] + (size_t)(kt + 1) * kstep[i]);
            CP_COMMIT();
            CP_WAIT(1);
        } else {
            CP_WAIT(0);
        }
        __syncthreads();

        const uint32_t st = sbase + (uint32_t)(s * STAGE_B);
#pragma unroll
        for (int kk = 0; kk < 4; kk++) {
            unsigned ah[4][4];
#pragma unroll
            for (int mf = 0; mf < 4; mf++) {
                uint32_t ra = st + ((a_row0 + mf * 16) * GLD + kk * 16 + a_koff) * 2;
                ldsm4(ah[mf], ra);
            }
            uint32_t kr = (uint32_t)(kk * 16 + ((t8 & 1) << 3) + l7);
            uint32_t sw7 = (kr & 7);
            uint32_t brow = st + APLANE_B + kr * 256;
#pragma unroll
            for (int g2 = 0; g2 < 2; g2++) {
                uint32_t bcol = (uint32_t)(wn * 4 + 2 * g2 + (t8 >> 1));
                unsigned bt[4];
                ldsm4t(bt, brow + ((bcol ^ sw7) << 4));
#pragma unroll
                for (int mf = 0; mf < 4; mf++) {
                    mma16816(acc[mf][2*g2],   ah[mf], bt[0], bt[1]);
                    mma16816(acc[mf][2*g2+1], ah[mf], bt[2], bt[3]);
                }
            }
        }
        __syncthreads();
    }

#pragma unroll
    for (int mf = 0; mf < 4; mf++)
#pragma unroll
        for (int nf = 0; nf < 4; nf++) {
            int row = bm + wm * 64 + mf * 16 + g;
            int col = bn + wn * 32 + nf * 8 + 2 * tig;
            float v0 = acc[mf][nf][0] * alpha, v1 = acc[mf][nf][1] * alpha;
            float v2 = acc[mf][nf][2] * alpha, v3 = acc[mf][nf][3] * alpha;
            if (Ch) {
                *reinterpret_cast<__half2*>(&Ch[(size_t)row*DIM+col])     = __halves2half2(__float2half_rn(v0), __float2half_rn(v1));
                *reinterpret_cast<__half2*>(&Ch[(size_t)(row+8)*DIM+col]) = __halves2half2(__float2half_rn(v2), __float2half_rn(v3));
            } else {
                *reinterpret_cast<float2*>(&C[(size_t)row*DIM+col])       = make_float2(v0,v1);
                *reinterpret_cast<float2*>(&C[(size_t)(row+8)*DIM+col])   = make_float2(v2,v3);
            }
        }
}

// fused Q/K/V projections: blockIdx.z selects operand set
__global__ __launch_bounds__(256, 2) void gemm_qkv()
{
    extern __shared__ __half sm[];
    int z = blockIdx.z;
    const __half* A  = (z == 0) ? g_Xqh : g_Xkh;
    const __half* Bn = (z == 0) ? g_Wqh : (z == 1) ? g_Wkh : g_Wvh;
    __half* Ch = (z == 0) ? g_Qh : (z == 1) ? g_Kh : g_Vh;
    float alpha = (z == 0) ? QSCALE : 1.0f;
    gemm_body(A, Bn, nullptr, Ch, alpha, sm);
}

// output projection: fp32 result
__global__ __launch_bounds__(256, 2) void gemm_o(float* __restrict__ out)
{
    extern __shared__ __half sm[];
    gemm_body(g_Cth, g_Woh, out, nullptr, 1.0f, sm);
}

// one fused elementwise fp32->fp16 conversion for all 6 tensors
// grid (4096, 12): z 0-3 = xq slices, 4-7 = xkv slices, 8-11 = weights
__global__ __launch_bounds__(256) void f2h_all(
    const float4* __restrict__ Xq, const float4* __restrict__ Xkv,
    const float4* __restrict__ W0, const float4* __restrict__ W1,
    const float4* __restrict__ W2, const float4* __restrict__ W3)
{
    int z = blockIdx.y;
    const float4* src; __half2* dst; unsigned slice;
    if (z < 4)      { src = Xq;  dst = reinterpret_cast<__half2*>(g_Xqh); slice = z; }
    else if (z < 8) { src = Xkv; dst = reinterpret_cast<__half2*>(g_Xkh); slice = z - 4; }
    else {
        src = (z == 8) ? W0 : (z == 9) ? W1 : (z == 10) ? W2 : W3;
        dst = reinterpret_cast<__half2*>((z == 8) ? g_Wqh : (z == 9) ? g_Wkh : (z == 10) ? g_Wvh : g_Woh);
        slice = 0;
    }
    size_t i = (size_t)slice * 1048576 + (size_t)blockIdx.x * 256 + threadIdx.x;
    float4 v = src[i];
    dst[2*i]   = __halves2half2(__float2half_rn(v.x), __float2half_rn(v.y));
    dst[2*i+1] = __halves2half2(__float2half_rn(v.z), __float2half_rn(v.w));
}

// =====================================================================
// flash2: FA-2. S = Qh*Kh (1-term). PV = P-hi*Vh (1-term). KT=128. (unchanged)
// 2 planes/stage {Kh, Vh} = 64KB; 2 stages = 128KB smem. 8 ktiles.
// =====================================================================
#define FSTG 65536

__global__ __launch_bounds__(256) void flash2()
{
    extern __shared__ char fs[];
    const uint32_t sb = smem_u32(fs);
    const int tid = threadIdx.x, lane = tid & 31, wid = tid >> 5;
    const int g = lane >> 2, tig = lane & 3;
    const int b = blockIdx.z, h = blockIdx.y, qt = blockIdx.x;
    const int t8 = lane >> 3, l7 = lane & 7;

    const size_t qrow0 = (size_t)(b * SEQ + qt * 128);
    const __half* Qg = g_Qh + qrow0 * DIM + h * HD;
    const size_t kvbase = (size_t)b * SEQ * DIM + h * HD;

    const __half* ksrc[16]; uint32_t kdst[16];
#pragma unroll
    for (int i = 0; i < 16; i++) {
        int p = i >> 3;
        int m = tid + 256 * (i & 7);
        int r = m >> 4, c = m & 15;
        const __half* base = (p == 0) ? g_Kh + kvbase : g_Vh + kvbase;
        ksrc[i] = base + (size_t)r * DIM + c * 8;
        kdst[i] = (uint32_t)(p * 32768 + r * 256 + ((c ^ (r & 7)) << 4));
    }

#pragma unroll
    for (int i = 0; i < 8; i++) {
        int n = tid + 256 * i;
        int r = n >> 4, c = n & 15;
        cp16(sb + FSTG + r * 256 + ((c ^ (r & 7)) << 4), Qg + (size_t)r * DIM + c * 8);
    }
    CP_COMMIT();
#pragma unroll
    for (int i = 0; i < 16; i++) cp16(sb + kdst[i], ksrc[i]);
    CP_COMMIT();

    CP_WAIT(1);
    __syncthreads();

    unsigned q[8][4];
#pragma unroll
    for (int kk = 0; kk < 8; kk++) {
        uint32_t row = (uint32_t)(wid * 16 + ((t8 & 1) << 3) + l7);
        uint32_t kc  = (uint32_t)(2 * kk + (t8 >> 1));
        ldsm4(q[kk], sb + FSTG + row * 256 + ((kc ^ (row & 7)) << 4));
    }
    __syncthreads();

    float o[16][4];
#pragma unroll
    for (int i = 0; i < 16; i++) { o[i][0]=o[i][1]=o[i][2]=o[i][3]=0.0f; }
    float m0 = -1e30f, m1 = -1e30f, l0 = 0.0f, l1 = 0.0f;

    for (int kt = 0; kt < SEQ / 128; kt++) {
        int s = kt & 1;
        if (kt + 1 < SEQ / 128) {
            uint32_t dst = sb + (uint32_t)((s ^ 1) * FSTG);
            size_t koff = (size_t)(kt + 1) * 128 * DIM;
#pragma unroll
            for (int i = 0; i < 16; i++) cp16(dst + kdst[i], ksrc[i] + koff);
            CP_COMMIT();
            CP_WAIT(1);
        } else {
            CP_WAIT(0);
        }
        __syncthreads();
        const uint32_t st = sb + (uint32_t)(s * FSTG);

        float sc[16][4];
#pragma unroll
        for (int nf = 0; nf < 16; nf++) { sc[nf][0]=sc[nf][1]=sc[nf][2]=sc[nf][3]=0.0f; }
#pragma unroll
        for (int kk = 0; kk < 8; kk++) {
#pragma unroll
            for (int nb = 0; nb < 8; nb++) {
                uint32_t n  = (uint32_t)(nb * 16 + ((t8 >> 1) << 3) + l7);
                uint32_t kc = (uint32_t)(2 * kk + (t8 & 1));
                uint32_t ak = st + n * 256 + ((kc ^ (n & 7)) << 4);
                unsigned bh[4];
                ldsm4(bh, ak);
                mma16816(sc[2*nb],   q[kk], bh[0], bh[1]);
                mma16816(sc[2*nb+1], q[kk], bh[2], bh[3]);
            }
        }

        float r0 = -1e30f, r1 = -1e30f;
#pragma unroll
        for (int nf = 0; nf < 16; nf++) { r0 = fmaxf(r0, fmaxf(sc[nf][0], sc[nf][1])); r1 = fmaxf(r1, fmaxf(sc[nf][2], sc[nf][3])); }
        r0 = fmaxf(r0, __shfl_xor_sync(~0u, r0, 1)); r0 = fmaxf(r0, __shfl_xor_sync(~0u, r0, 2));
        r1 = fmaxf(r1, __shfl_xor_sync(~0u, r1, 1)); r1 = fmaxf(r1, __shfl_xor_sync(~0u, r1, 2));
        float mn0 = fmaxf(m0, r0), mn1 = fmaxf(m1, r1);
        float f0 = __expf(m0 - mn0), f1 = __expf(m1 - mn1);
        m0 = mn0; m1 = mn1;
        float rs0 = 0.0f, rs1 = 0.0f;
#pragma unroll
        for (int nf = 0; nf < 16; nf++) {
            sc[nf][0] = __expf(sc[nf][0] - m0); sc[nf][1] = __expf(sc[nf][1] - m0);
            sc[nf][2] = __expf(sc[nf][2] - m1); sc[nf][3] = __expf(sc[nf][3] - m1);
            rs0 += sc[nf][0] + sc[nf][1]; rs1 += sc[nf][2] + sc[nf][3];
        }
        rs0 += __shfl_xor_sync(~0u, rs0, 1); rs0 += __shfl_xor_sync(~0u, rs0, 2);
        rs1 += __shfl_xor_sync(~0u, rs1, 1); rs1 += __shfl_xor_sync(~0u, rs1, 2);
        l0 = l0 * f0 + rs0; l1 = l1 * f1 + rs1;
#pragma unroll
        for (int nf = 0; nf < 16; nf++) { o[nf][0] *= f0; o[nf][1] *= f0; o[nf][2] *= f1; o[nf][3] *= f1; }

#pragma unroll
        for (int kk2 = 0; kk2 < 8; kk2++) {
            const int j0 = 2*kk2, j1 = 2*kk2 + 1;
            unsigned ah_[4] = {
                pack_h2(__float2half_rn(sc[j0][0]), __float2half_rn(sc[j0][1])),
                pack_h2(__float2half_rn(sc[j0][2]), __float2half_rn(sc[j0][3])),
                pack_h2(__float2half_rn(sc[j1][0]), __float2half_rn(sc[j1][1])),
                pack_h2(__float2half_rn(sc[j1][2]), __float2half_rn(sc[j1][3]))};
            uint32_t kr = (uint32_t)(kk2 * 16 + ((t8 & 1) << 3) + l7);
            uint32_t vrow = st + 32768 + kr * 256;
            uint32_t sw7 = (kr & 7);
#pragma unroll
            for (int na = 0; na < 8; na++) {
                uint32_t nblk = (uint32_t)(2 * na + (t8 >> 1));
                uint32_t av = vrow + ((nblk ^ sw7) << 4);
                unsigned vh[4];
                ldsm4t(vh, av);
                mma16816(o[2*na],   ah_, vh[0], vh[1]);
                mma16816(o[2*na+1], ah_, vh[2], vh[3]);
            }
        }
        __syncthreads();
    }

    float i0 = 1.0f / l0, i1 = 1.0f / l1;
    const size_t row = qrow0 + wid * 16 + g;
    __half* Ch = g_Cth + row * DIM + h * HD;
#pragma unroll
    for (int nf2 = 0; nf2 < 16; nf2++) {
        int c = nf2 * 8 + 2 * tig;
        float v0 = o[nf2][0] * i0, v1 = o[nf2][1] * i0;
        float v2 = o[nf2][2] * i1, v3 = o[nf2][3] * i1;
        *reinterpret_cast<__half2*>(Ch + c)         = __halves2half2(__float2half_rn(v0), __float2half_rn(v1));
        *reinterpret_cast<__half2*>(Ch + 8*DIM + c) = __halves2half2(__float2half_rn(v2), __float2half_rn(v3));
    }
}

// =====================================================================
extern "C" void kernel_launch(void* const* d_in, const int* in_sizes, int n_in,
                              void* d_out, int out_size)
{
    const float* xq  = (const float*)d_in[0];
    const float* xkv = (const float*)d_in[1];
    const float* Wq  = (const float*)d_in[2];
    const float* Wk  = (const float*)d_in[3];
    const float* Wv  = (const float*)d_in[4];
    const float* Wo  = (const float*)d_in[5];
    float* out = (float*)d_out;

    f2h_all<<<dim3(4096, 12), 256>>>((const float4*)xq, (const float4*)xkv,
                                     (const float4*)Wq, (const float4*)Wk,
                                     (const float4*)Wv, (const float4*)Wo);

    cudaFuncSetAttribute(gemm_qkv, cudaFuncAttributeMaxDynamicSharedMemorySize, GEMM_SMEM);
    cudaFuncSetAttribute(gemm_o,   cudaFuncAttributeMaxDynamicSharedMemorySize, GEMM_SMEM);
    gemm_qkv<<<dim3(DIM/128, MROWS/128, 3), 256, GEMM_SMEM>>>();

    cudaFuncSetAttribute(flash2, cudaFuncAttributeMaxDynamicSharedMemorySize, 2 * FSTG);
    flash2<<<dim3(SEQ/128, HEADS, BATCH), 256, 2 * FSTG>>>();

    gemm_o<<<dim3(DIM/128, MROWS/128), 256, GEMM_SMEM>>>(out);
}